// round 9
// baseline (speedup 1.0000x reference)
#include <cuda_runtime.h>
#include <cuda_fp16.h>
#include <math.h>
#include <stdint.h>

#define CEMB 1024
#define NHEADS 16
#define HS 64
#define DFF 4096
#define BB 4
#define TT 2048
#define MROWS (BB*TT)   // 8192

#define BM 128
#define BN 256
#define BKE 64
#define GT 256

// ---------------- scratch ----------------
__device__ __half g_qkv[(size_t)MROWS * 3 * CEMB];  // fp16 qkv
__device__ float g_x2 [(size_t)MROWS * CEMB];
__device__ __half g_h [(size_t)MROWS * CEMB];       // ln out
__device__ __half g_y [(size_t)MROWS * CEMB];       // attn out
__device__ __half g_f [(size_t)MROWS * DFF];        // mlp hidden
// weights, transposed to [N,K] K-major, fp16
__device__ __half g_wa[(size_t)3*CEMB * CEMB];
__device__ __half g_wp[(size_t)CEMB * CEMB];
__device__ __half g_wf[(size_t)DFF * CEMB];
__device__ __half g_w2[(size_t)CEMB * DFF];
// attention operands
__device__ __half g_aq[(size_t)64 * TT * HS];
__device__ __half g_ak[(size_t)64 * TT * HS];
__device__ __half g_av[(size_t)64 * HS * TT];       // V transposed [bh][d][t]

// ---------------- PTX helpers ----------------
__device__ __forceinline__ uint32_t smem_u32(const void* p) {
    uint32_t a;
    asm("{ .reg .u64 t; cvta.to.shared.u64 t, %1; cvt.u32.u64 %0, t; }" : "=r"(a) : "l"(p));
    return a;
}
#define CP_ASYNC16(s, g) \
    asm volatile("cp.async.cg.shared.global [%0], [%1], 16;" :: "r"(s), "l"(g) : "memory")
#define CP_COMMIT() asm volatile("cp.async.commit_group;" ::: "memory")
#define CP_WAIT1()  asm volatile("cp.async.wait_group 1;" ::: "memory")
#define CP_WAIT0()  asm volatile("cp.async.wait_group 0;" ::: "memory")
#define LDSM_X4(r0, r1, r2, r3, addr) \
    asm volatile("ldmatrix.sync.aligned.m8n8.x4.shared.b16 {%0,%1,%2,%3}, [%4];" \
        : "=r"(r0), "=r"(r1), "=r"(r2), "=r"(r3) : "r"(addr))
#define MMAF16(c, a, b0v, b1v) \
    asm volatile("mma.sync.aligned.m16n8k16.row.col.f32.f16.f16.f32 " \
        "{%0,%1,%2,%3}, {%4,%5,%6,%7}, {%8,%9}, {%0,%1,%2,%3};" \
        : "+f"((c)[0]), "+f"((c)[1]), "+f"((c)[2]), "+f"((c)[3]) \
        : "r"((a)[0]), "r"((a)[1]), "r"((a)[2]), "r"((a)[3]), "r"(b0v), "r"(b1v))
#define STS32(addr, v) \
    asm volatile("st.shared.b32 [%0], %1;" :: "r"(addr), "r"(v) : "memory")

__device__ __forceinline__ uint32_t sw128(uint32_t off) { return off ^ ((off >> 3) & 0x70); }

__device__ __forceinline__ float gelu_f(float x) {
    float t = tanhf(0.79788456080286536f * (x + 0.044715f * x * x * x));
    return 0.5f * x * (1.0f + t);
}

union H4 { __half h[4]; uint2 u; };
union H2 { __half h[2]; uint32_t u; };

// ---------------- weight transpose + fp16 convert ----------------
__global__ __launch_bounds__(256) void wconv_kernel(const float* __restrict__ W,
    __half* __restrict__ Wf, int K, int N)
{
    __shared__ float t[32][33];
    int n0 = blockIdx.x * 32, k0 = blockIdx.y * 32;
    int tx = threadIdx.x & 31, ty = threadIdx.x >> 5;
    #pragma unroll
    for (int r = ty; r < 32; r += 8)
        t[r][tx] = W[(size_t)(k0 + r) * N + n0 + tx];
    __syncthreads();
    #pragma unroll
    for (int r = ty; r < 32; r += 8)
        Wf[(size_t)(n0 + r) * K + k0 + tx] = __float2half(t[tx][r]);
}

// ---------------- LayerNorm -> fp16 ----------------
__global__ __launch_bounds__(256) void ln_kernel(const float* __restrict__ x,
                                                 const float* __restrict__ g,
                                                 const float* __restrict__ b,
                                                 __half* __restrict__ oh)
{
    int row = blockIdx.x;
    int t = threadIdx.x;
    float4 v = ((const float4*)(x + (size_t)row * CEMB))[t];
    float s  = v.x + v.y + v.z + v.w;
    float ss = v.x*v.x + v.y*v.y + v.z*v.z + v.w*v.w;
    #pragma unroll
    for (int o = 16; o > 0; o >>= 1) {
        s  += __shfl_xor_sync(0xffffffffu, s,  o);
        ss += __shfl_xor_sync(0xffffffffu, ss, o);
    }
    __shared__ float red[16];
    int warp = t >> 5, lane = t & 31;
    if (lane == 0) { red[warp] = s; red[warp + 8] = ss; }
    __syncthreads();
    float sum = 0.f, sumsq = 0.f;
    #pragma unroll
    for (int w = 0; w < 8; w++) { sum += red[w]; sumsq += red[w + 8]; }
    float mu   = sum * (1.0f / CEMB);
    float var  = sumsq * (1.0f / CEMB) - mu * mu;
    float rstd = rsqrtf(var + 1e-5f);
    float4 gv = ((const float4*)g)[t];
    float4 bv = ((const float4*)b)[t];
    H4 o;
    o.h[0] = __float2half((v.x - mu) * rstd * gv.x + bv.x);
    o.h[1] = __float2half((v.y - mu) * rstd * gv.y + bv.y);
    o.h[2] = __float2half((v.z - mu) * rstd * gv.z + bv.z);
    o.h[3] = __float2half((v.w - mu) * rstd * gv.w + bv.w);
    *(uint2*)(oh + (size_t)row * CEMB + t * 4) = o.u;
}

// ---------------- HMMA fp16 GEMM: C = A @ B^T + bias ----------------
// tile 128x256, 8 warps (2m x 4n), warp tile 64x64. 2-stage cp.async.
// stage: A 16K | B 32K = 48KB -> 96KB, occ 1.
// EPI: 1 = fp32 out + residual, 2 = gelu -> fp16, 4 = plain fp16 out
#define STAGE_BYTES 49152
#define SMEM_GEMM (2 * STAGE_BYTES + 1024)

template<int EPI>
__global__ __launch_bounds__(GT, 1) void gemm_f16(
    const __half* __restrict__ Ah,
    const __half* __restrict__ Bf,
    const float* __restrict__ bias, const float* __restrict__ R,
    float* __restrict__ Cf, __half* __restrict__ Ch,
    int M, int N, int K)
{
    extern __shared__ char dsm[];
    uintptr_t pa = ((uintptr_t)dsm + 1023) & ~(uintptr_t)1023;
    uint32_t sb = smem_u32((char*)pa);

    int tid = threadIdx.x;
    int wid = tid >> 5, lid = tid & 31;
    int wm = wid >> 2, wn = wid & 3;
    int m0 = blockIdx.y * BM, n0 = blockIdx.x * BN;

    const int NC = K / BKE;
    int lrow = tid >> 3;
    int lch  = tid & 7;

    auto load_stage = [&](int c) {
        int buf = c & 1;
        uint32_t st = sb + buf * STAGE_BYTES;
        int k0 = c * BKE;
        #pragma unroll
        for (int t = 0; t < 4; t++) {
            int row = lrow + t * 32;
            uint32_t so = sw128((uint32_t)(row * 128 + lch * 16));
            size_t ga = (size_t)(m0 + row) * K + k0 + lch * 8;
            CP_ASYNC16(st + so, (const char*)(Ah + ga));
        }
        #pragma unroll
        for (int t = 0; t < 8; t++) {
            int row = lrow + t * 32;
            uint32_t so = sw128((uint32_t)(row * 128 + lch * 16));
            size_t gb = (size_t)(n0 + row) * K + k0 + lch * 8;
            CP_ASYNC16(st + 16384 + so, (const char*)(Bf + gb));
        }
    };

    float acc[4][8][4];
    #pragma unroll
    for (int mi = 0; mi < 4; mi++)
        #pragma unroll
        for (int j = 0; j < 8; j++)
            #pragma unroll
            for (int q = 0; q < 4; q++) acc[mi][j][q] = 0.f;

    int lrow16 = lid & 15;
    int khalf  = lid >> 4;

    load_stage(0);
    CP_COMMIT();

    for (int c = 0; c < NC; c++) {
        if (c + 1 < NC) { load_stage(c + 1); CP_COMMIT(); CP_WAIT1(); }
        else            { CP_WAIT0(); }
        __syncthreads();

        uint32_t st = sb + (c & 1) * STAGE_BYTES;

        #pragma unroll
        for (int s = 0; s < 4; s++) {
            uint32_t aH[4][4], bH[4][4];
            #pragma unroll
            for (int mi = 0; mi < 4; mi++) {
                int row = wm * 64 + mi * 16 + lrow16;
                int ch = (s * 2 + khalf) ^ (row & 7);
                uint32_t ad = st + (uint32_t)(row * 128 + ch * 16);
                LDSM_X4(aH[mi][0], aH[mi][1], aH[mi][2], aH[mi][3], ad);
            }
            #pragma unroll
            for (int nb = 0; nb < 4; nb++) {
                int row = wn * 64 + nb * 16 + lrow16;
                int ch = (s * 2 + khalf) ^ (row & 7);
                uint32_t bd = st + 16384 + (uint32_t)(row * 128 + ch * 16);
                LDSM_X4(bH[nb][0], bH[nb][1], bH[nb][2], bH[nb][3], bd);
            }
            #pragma unroll
            for (int mi = 0; mi < 4; mi++) {
                #pragma unroll
                for (int nb = 0; nb < 4; nb++) {
                    MMAF16(acc[mi][nb*2],   aH[mi], bH[nb][0], bH[nb][2]);
                    MMAF16(acc[mi][nb*2+1], aH[mi], bH[nb][1], bH[nb][3]);
                }
            }
        }
        __syncthreads();
    }

    int gid = lid >> 2, tig = lid & 3;
    #pragma unroll
    for (int mi = 0; mi < 4; mi++) {
        #pragma unroll
        for (int j = 0; j < 8; j++) {
            int r0 = m0 + wm * 64 + mi * 16 + gid;
            int r1 = r0 + 8;
            int col = n0 + wn * 64 + j * 8 + tig * 2;
            float b0 = bias[col], b1 = bias[col + 1];
            float v0 = acc[mi][j][0] + b0, v1 = acc[mi][j][1] + b1;
            float v2 = acc[mi][j][2] + b0, v3 = acc[mi][j][3] + b1;
            if (EPI == 1) {
                float2 q0 = *(const float2*)(R + (size_t)r0 * N + col);
                float2 q1 = *(const float2*)(R + (size_t)r1 * N + col);
                v0 += q0.x; v1 += q0.y; v2 += q1.x; v3 += q1.y;
            }
            if (EPI == 2) {
                v0 = gelu_f(v0); v1 = gelu_f(v1); v2 = gelu_f(v2); v3 = gelu_f(v3);
            }
            if (EPI == 2 || EPI == 4) {
                H2 h0, h1;
                h0.h[0] = __float2half(v0); h0.h[1] = __float2half(v1);
                h1.h[0] = __float2half(v2); h1.h[1] = __float2half(v3);
                *(uint32_t*)(Ch + (size_t)r0 * N + col) = h0.u;
                *(uint32_t*)(Ch + (size_t)r1 * N + col) = h1.u;
            } else {
                *(float2*)(Cf + (size_t)r0 * N + col) = make_float2(v0, v1);
                *(float2*)(Cf + (size_t)r1 * N + col) = make_float2(v2, v3);
            }
        }
    }
}

// ---------------- attention prep (fp16 qkv input) ----------------
__global__ __launch_bounds__(256) void attnprep_kernel(
    const __half* __restrict__ qkv,
    __half* __restrict__ Qf, __half* __restrict__ Kf, __half* __restrict__ Vt)
{
    __shared__ float vs[64][65];
    int tb = blockIdx.x, bh = blockIdx.y;
    int b = bh >> 4, hd = bh & 15;
    int t0 = tb * 64;
    int tid = threadIdx.x;

    for (int i = tid; i < 1024; i += 256) {
        int r = i >> 4, c4 = (i & 15) * 4;
        const __half* base = qkv + ((size_t)(b * TT + t0 + r)) * (3 * CEMB) + hd * HS + c4;
        H4 q, k, v;
        q.u = *(const uint2*)base;
        k.u = *(const uint2*)(base + CEMB);
        v.u = *(const uint2*)(base + 2 * CEMB);
        H4 qq;
        #pragma unroll
        for (int j = 0; j < 4; j++)
            qq.h[j] = __float2half(__half2float(q.h[j]) * 0.125f);
        size_t qo = ((size_t)bh * TT + t0 + r) * HS + c4;
        *(uint2*)(Qf + qo) = qq.u;
        *(uint2*)(Kf + qo) = k.u;
        vs[r][c4]   = __half2float(v.h[0]);
        vs[r][c4+1] = __half2float(v.h[1]);
        vs[r][c4+2] = __half2float(v.h[2]);
        vs[r][c4+3] = __half2float(v.h[3]);
    }
    __syncthreads();
    for (int i = tid; i < 1024; i += 256) {
        int d = i >> 4, tq = (i & 15) * 4;
        H4 vv;
        vv.h[0] = __float2half(vs[tq+0][d]);
        vv.h[1] = __float2half(vs[tq+1][d]);
        vv.h[2] = __float2half(vs[tq+2][d]);
        vv.h[3] = __float2half(vs[tq+3][d]);
        size_t vo = ((size_t)bh * HS + d) * TT + t0 + tq;
        *(uint2*)(Vt + vo) = vv.u;
    }
}

// ---------------- HMMA flash attention (all fp16, 2-stage as R6 champion) ----------------
// smem: Q 16K @0 | buf(b) @16K+16K*b: K 8K, Vt 8K | P 16K @48K = 64KB
#define ATSM_BUF(b) (16384 + (b) * 16384)
#define ATSM_P 49152
#define ATT_SMEM (65536 + 1024)

__global__ __launch_bounds__(256, 2) void attn_mma_kernel(
    const __half* __restrict__ Qf_, const __half* __restrict__ Kf_,
    const __half* __restrict__ Vt_,
    __half* __restrict__ yo)
{
    extern __shared__ char dsm[];
    uintptr_t pa = ((uintptr_t)dsm + 1023) & ~(uintptr_t)1023;
    uint32_t sb = smem_u32((char*)pa);

    int qt = gridDim.x - 1 - blockIdx.x;
    int q0 = qt * 128;
    int bh = blockIdx.y;
    int b = bh >> 4, hd = bh & 15;
    size_t hq = (size_t)bh * TT * HS;

    int tid = threadIdx.x;
    int wid = tid >> 5, lid = tid & 31;
    int lrow16 = lid & 15, khalf = lid >> 4;
    int arow = wid * 16 + lrow16;

    auto load_kv = [&](int jb, int buf) {
        int j0 = jb * 64;
        uint32_t st = sb + ATSM_BUF(buf);
        const char* kf = (const char*)(Kf_ + hq + (size_t)j0 * HS);
        const char* vt = (const char*)(Vt_ + hq) + (size_t)j0 * 2;
        #pragma unroll
        for (int i = tid; i < 512; i += 256) {
            int row = i >> 3, ch = i & 7;
            uint32_t so = sw128((uint32_t)(row * 128 + ch * 16));
            CP_ASYNC16(st + so,        kf + row * 128 + ch * 16);
            CP_ASYNC16(st + 8192 + so, vt + (size_t)row * (TT * 2) + ch * 16);
        }
    };

    {
        const char* qf = (const char*)(Qf_ + hq + (size_t)q0 * HS);
        #pragma unroll
        for (int i = tid; i < 1024; i += 256) {
            int row = i >> 3, ch = i & 7;
            uint32_t so = sw128((uint32_t)(row * 128 + ch * 16));
            CP_ASYNC16(sb + so, qf + row * 128 + ch * 16);
        }
    }
    load_kv(0, 0);
    CP_COMMIT();

    float m_[2] = {-INFINITY, -INFINITY};
    float l_[2] = {0.f, 0.f};
    float acc[8][4];
    #pragma unroll
    for (int nb = 0; nb < 8; nb++)
        #pragma unroll
        for (int q = 0; q < 4; q++) acc[nb][q] = 0.f;

    int jbmax = q0 / 64 + 1;
    for (int jb = 0; jb <= jbmax; jb++) {
        int buf = jb & 1;
        CP_WAIT0();
        __syncthreads();
        if (jb < jbmax) { load_kv(jb + 1, buf ^ 1); CP_COMMIT(); }

        uint32_t sK = sb + ATSM_BUF(buf);
        uint32_t sV = sK + 8192;

        float s[8][4];
        #pragma unroll
        for (int nb = 0; nb < 8; nb++)
            #pragma unroll
            for (int q = 0; q < 4; q++) s[nb][q] = 0.f;

        #pragma unroll
        for (int ks = 0; ks < 4; ks++) {
            int ach = (ks * 2 + khalf) ^ (arow & 7);
            uint32_t aa = sb + (uint32_t)(arow * 128 + ach * 16);
            uint32_t aH[4];
            LDSM_X4(aH[0], aH[1], aH[2], aH[3], aa);
            uint32_t bH[4][4];
            #pragma unroll
            for (int nb2 = 0; nb2 < 4; nb2++) {
                int br = nb2 * 16 + lrow16;
                int bch = (ks * 2 + khalf) ^ (br & 7);
                uint32_t ba = sK + (uint32_t)(br * 128 + bch * 16);
                LDSM_X4(bH[nb2][0], bH[nb2][1], bH[nb2][2], bH[nb2][3], ba);
            }
            #pragma unroll
            for (int nb2 = 0; nb2 < 4; nb2++) {
                MMAF16(s[nb2*2],   aH, bH[nb2][0], bH[nb2][2]);
                MMAF16(s[nb2*2+1], aH, bH[nb2][1], bH[nb2][3]);
            }
        }

        int j0 = jb * 64;
        if (j0 + 63 > q0 + wid * 16) {
            int r0g = q0 + wid * 16 + (lid >> 2);
            #pragma unroll
            for (int nb = 0; nb < 8; nb++) {
                int c0 = j0 + nb * 8 + (lid & 3) * 2;
                if (c0     > r0g)     s[nb][0] = -INFINITY;
                if (c0 + 1 > r0g)     s[nb][1] = -INFINITY;
                if (c0     > r0g + 8) s[nb][2] = -INFINITY;
                if (c0 + 1 > r0g + 8) s[nb][3] = -INFINITY;
            }
        }

        float rmax[2] = {-INFINITY, -INFINITY};
        #pragma unroll
        for (int nb = 0; nb < 8; nb++) {
            rmax[0] = fmaxf(rmax[0], fmaxf(s[nb][0], s[nb][1]));
            rmax[1] = fmaxf(rmax[1], fmaxf(s[nb][2], s[nb][3]));
        }
        #pragma unroll
        for (int o = 1; o <= 2; o <<= 1) {
            rmax[0] = fmaxf(rmax[0], __shfl_xor_sync(0xffffffffu, rmax[0], o));
            rmax[1] = fmaxf(rmax[1], __shfl_xor_sync(0xffffffffu, rmax[1], o));
        }
        float mn0 = fmaxf(m_[0], rmax[0]);
        float mn1 = fmaxf(m_[1], rmax[1]);
        float alpha0 = __expf(m_[0] - mn0);
        float alpha1 = __expf(m_[1] - mn1);
        m_[0] = mn0; m_[1] = mn1;
        float rs[2] = {0.f, 0.f};
        #pragma unroll
        for (int nb = 0; nb < 8; nb++) {
            s[nb][0] = __expf(s[nb][0] - mn0); rs[0] += s[nb][0];
            s[nb][1] = __expf(s[nb][1] - mn0); rs[0] += s[nb][1];
            s[nb][2] = __expf(s[nb][2] - mn1); rs[1] += s[nb][2];
            s[nb][3] = __expf(s[nb][3] - mn1); rs[1] += s[nb][3];
        }
        #pragma unroll
        for (int o = 1; o <= 2; o <<= 1) {
            rs[0] += __shfl_xor_sync(0xffffffffu, rs[0], o);
            rs[1] += __shfl_xor_sync(0xffffffffu, rs[1], o);
        }
        l_[0] = l_[0] * alpha0 + rs[0];
        l_[1] = l_[1] * alpha1 + rs[1];
        #pragma unroll
        for (int nb = 0; nb < 8; nb++) {
            acc[nb][0] *= alpha0; acc[nb][1] *= alpha0;
            acc[nb][2] *= alpha1; acc[nb][3] *= alpha1;
        }

        {
            int r0 = wid * 16 + (lid >> 2);
            #pragma unroll
            for (int nb = 0; nb < 8; nb++) {
                int coff = (nb * 8 + (lid & 3) * 2) * 2;
                uint32_t o0 = sw128((uint32_t)(r0 * 128 + coff));
                uint32_t o1 = sw128((uint32_t)((r0 + 8) * 128 + coff));
                H2 h;
                h.h[0] = __float2half(s[nb][0]); h.h[1] = __float2half(s[nb][1]);
                STS32(sb + ATSM_P + o0, h.u);
                h.h[0] = __float2half(s[nb][2]); h.h[1] = __float2half(s[nb][3]);
                STS32(sb + ATSM_P + o1, h.u);
            }
        }
        __syncwarp();

        #pragma unroll
        for (int ks = 0; ks < 4; ks++) {
            int ach = (ks * 2 + khalf) ^ (arow & 7);
            uint32_t paddr = sb + ATSM_P + (uint32_t)(arow * 128 + ach * 16);
            uint32_t pH[4];
            LDSM_X4(pH[0], pH[1], pH[2], pH[3], paddr);
            uint32_t bH[4][4];
            #pragma unroll
            for (int nb2 = 0; nb2 < 4; nb2++) {
                int br = nb2 * 16 + lrow16;
                int bch = (ks * 2 + khalf) ^ (br & 7);
                uint32_t ba = sV + (uint32_t)(br * 128 + bch * 16);
                LDSM_X4(bH[nb2][0], bH[nb2][1], bH[nb2][2], bH[nb2][3], ba);
            }
            #pragma unroll
            for (int nb2 = 0; nb2 < 4; nb2++) {
                MMAF16(acc[nb2*2],   pH, bH[nb2][0], bH[nb2][2]);
                MMAF16(acc[nb2*2+1], pH, bH[nb2][1], bH[nb2][3]);
            }
        }
    }

    float inv0 = 1.0f / l_[0];
    float inv1 = 1.0f / l_[1];
    size_t r0g = (size_t)b * TT + q0 + wid * 16 + (lid >> 2);
    #pragma unroll
    for (int nb = 0; nb < 8; nb++) {
        int col = hd * HS + nb * 8 + (lid & 3) * 2;
        H2 h;
        h.h[0] = __float2half(acc[nb][0] * inv0);
        h.h[1] = __float2half(acc[nb][1] * inv0);
        *(uint32_t*)(yo + r0g * CEMB + col) = h.u;
        h.h[0] = __float2half(acc[nb][2] * inv1);
        h.h[1] = __float2half(acc[nb][3] * inv1);
        *(uint32_t*)(yo + (r0g + 8) * CEMB + col) = h.u;
    }
}

// ---------------- launch ----------------
extern "C" void kernel_launch(void* const* d_in, const int* in_sizes, int n_in,
                              void* d_out, int out_size)
{
    const float* x      = (const float*)d_in[0];
    const float* ln1_g  = (const float*)d_in[1];
    const float* ln1_b  = (const float*)d_in[2];
    const float* w_attn = (const float*)d_in[3];
    const float* b_attn = (const float*)d_in[4];
    const float* w_proj = (const float*)d_in[5];
    const float* b_proj = (const float*)d_in[6];
    const float* ln2_g  = (const float*)d_in[7];
    const float* ln2_b  = (const float*)d_in[8];
    const float* w_fc   = (const float*)d_in[9];
    const float* b_fc   = (const float*)d_in[10];
    const float* w_fc2  = (const float*)d_in[11];
    const float* b_fc2  = (const float*)d_in[12];
    float* out = (float*)d_out;

    float *x2;
    __half *qkv, *h, *y, *f;
    __half *wa, *wp, *wf, *w2;
    __half *aq, *ak, *av;
    cudaGetSymbolAddress((void**)&qkv, g_qkv);
    cudaGetSymbolAddress((void**)&x2,  g_x2);
    cudaGetSymbolAddress((void**)&h,   g_h);
    cudaGetSymbolAddress((void**)&y,   g_y);
    cudaGetSymbolAddress((void**)&f,   g_f);
    cudaGetSymbolAddress((void**)&wa,  g_wa);
    cudaGetSymbolAddress((void**)&wp,  g_wp);
    cudaGetSymbolAddress((void**)&wf,  g_wf);
    cudaGetSymbolAddress((void**)&w2,  g_w2);
    cudaGetSymbolAddress((void**)&aq,  g_aq);
    cudaGetSymbolAddress((void**)&ak,  g_ak);
    cudaGetSymbolAddress((void**)&av,  g_av);

    cudaFuncSetAttribute(gemm_f16<1>, cudaFuncAttributeMaxDynamicSharedMemorySize, SMEM_GEMM);
    cudaFuncSetAttribute(gemm_f16<2>, cudaFuncAttributeMaxDynamicSharedMemorySize, SMEM_GEMM);
    cudaFuncSetAttribute(gemm_f16<4>, cudaFuncAttributeMaxDynamicSharedMemorySize, SMEM_GEMM);
    cudaFuncSetAttribute(attn_mma_kernel, cudaFuncAttributeMaxDynamicSharedMemorySize, ATT_SMEM);

    dim3 blk(256);

    wconv_kernel<<<dim3(3*CEMB/32, CEMB/32), blk>>>(w_attn, wa, CEMB, 3*CEMB);
    wconv_kernel<<<dim3(CEMB/32,   CEMB/32), blk>>>(w_proj, wp, CEMB, CEMB);
    wconv_kernel<<<dim3(DFF/32,    CEMB/32), blk>>>(w_fc,   wf, CEMB, DFF);
    wconv_kernel<<<dim3(CEMB/32,   DFF/32),  blk>>>(w_fc2,  w2, DFF,  CEMB);

    ln_kernel<<<MROWS, blk>>>(x, ln1_g, ln1_b, h);
    // qkv (fp16 out)
    gemm_f16<4><<<dim3(3*CEMB/BN, MROWS/BM), GT, SMEM_GEMM>>>(
        h, wa, b_attn, nullptr, nullptr, qkv, MROWS, 3*CEMB, CEMB);
    attnprep_kernel<<<dim3(TT/64, BB*NHEADS), blk>>>(qkv, aq, ak, av);
    attn_mma_kernel<<<dim3(TT/128, BB*NHEADS), blk, ATT_SMEM>>>(aq, ak, av, y);
    gemm_f16<1><<<dim3(CEMB/BN, MROWS/BM), GT, SMEM_GEMM>>>(
        y, wp, b_proj, x, x2, nullptr, MROWS, CEMB, CEMB);
    ln_kernel<<<MROWS, blk>>>(x2, ln2_g, ln2_b, h);
    gemm_f16<2><<<dim3(DFF/BN, MROWS/BM), GT, SMEM_GEMM>>>(
        h, wf, b_fc, nullptr, nullptr, f, MROWS, DFF, CEMB);
    gemm_f16<1><<<dim3(CEMB/BN, MROWS/BM), GT, SMEM_GEMM>>>(
        f, w2, b_fc2, x2, out, nullptr, MROWS, CEMB, DFF);
}

// round 10
// speedup vs baseline: 1.1183x; 1.1183x over previous
#include <cuda_runtime.h>
#include <cuda_fp16.h>
#include <math.h>
#include <stdint.h>

#define CEMB 1024
#define NHEADS 16
#define HS 64
#define DFF 4096
#define BB 4
#define TT 2048
#define MROWS (BB*TT)   // 8192
#define RS (3*CEMB)     // qkv row stride (elements)

#define BM 128
#define BN 128
#define BKE 64
#define GT 256

// ---------------- scratch ----------------
__device__ __half g_qkv[(size_t)MROWS * 3 * CEMB];  // fp16 qkv, q pre-scaled 0.125
__device__ float g_x2 [(size_t)MROWS * CEMB];
__device__ __half g_h [(size_t)MROWS * CEMB];       // ln out
__device__ __half g_y [(size_t)MROWS * CEMB];       // attn out
__device__ __half g_f [(size_t)MROWS * DFF];        // mlp hidden
// weights, transposed to [N,K] K-major, fp16
__device__ __half g_wa[(size_t)3*CEMB * CEMB];
__device__ __half g_wp[(size_t)CEMB * CEMB];
__device__ __half g_wf[(size_t)DFF * CEMB];
__device__ __half g_w2[(size_t)CEMB * DFF];

// ---------------- PTX helpers ----------------
__device__ __forceinline__ uint32_t smem_u32(const void* p) {
    uint32_t a;
    asm("{ .reg .u64 t; cvta.to.shared.u64 t, %1; cvt.u32.u64 %0, t; }" : "=r"(a) : "l"(p));
    return a;
}
#define CP_ASYNC16(s, g) \
    asm volatile("cp.async.cg.shared.global [%0], [%1], 16;" :: "r"(s), "l"(g) : "memory")
#define CP_COMMIT() asm volatile("cp.async.commit_group;" ::: "memory")
#define CP_WAIT1()  asm volatile("cp.async.wait_group 1;" ::: "memory")
#define CP_WAIT0()  asm volatile("cp.async.wait_group 0;" ::: "memory")
#define LDSM_X4(r0, r1, r2, r3, addr) \
    asm volatile("ldmatrix.sync.aligned.m8n8.x4.shared.b16 {%0,%1,%2,%3}, [%4];" \
        : "=r"(r0), "=r"(r1), "=r"(r2), "=r"(r3) : "r"(addr))
#define LDSM_X4_T(r0, r1, r2, r3, addr) \
    asm volatile("ldmatrix.sync.aligned.m8n8.x4.trans.shared.b16 {%0,%1,%2,%3}, [%4];" \
        : "=r"(r0), "=r"(r1), "=r"(r2), "=r"(r3) : "r"(addr))
#define MMAF16(c, a, b0v, b1v) \
    asm volatile("mma.sync.aligned.m16n8k16.row.col.f32.f16.f16.f32 " \
        "{%0,%1,%2,%3}, {%4,%5,%6,%7}, {%8,%9}, {%0,%1,%2,%3};" \
        : "+f"((c)[0]), "+f"((c)[1]), "+f"((c)[2]), "+f"((c)[3]) \
        : "r"((a)[0]), "r"((a)[1]), "r"((a)[2]), "r"((a)[3]), "r"(b0v), "r"(b1v))
#define STS32(addr, v) \
    asm volatile("st.shared.b32 [%0], %1;" :: "r"(addr), "r"(v) : "memory")

__device__ __forceinline__ uint32_t sw128(uint32_t off) { return off ^ ((off >> 3) & 0x70); }

__device__ __forceinline__ float gelu_f(float x) {
    float t = tanhf(0.79788456080286536f * (x + 0.044715f * x * x * x));
    return 0.5f * x * (1.0f + t);
}

union H4 { __half h[4]; uint2 u; };
union H2 { __half h[2]; uint32_t u; };

// ---------------- weight transpose + fp16 convert ----------------
__global__ __launch_bounds__(256) void wconv_kernel(const float* __restrict__ W,
    __half* __restrict__ Wf, int K, int N)
{
    __shared__ float t[32][33];
    int n0 = blockIdx.x * 32, k0 = blockIdx.y * 32;
    int tx = threadIdx.x & 31, ty = threadIdx.x >> 5;
    #pragma unroll
    for (int r = ty; r < 32; r += 8)
        t[r][tx] = W[(size_t)(k0 + r) * N + n0 + tx];
    __syncthreads();
    #pragma unroll
    for (int r = ty; r < 32; r += 8)
        Wf[(size_t)(n0 + r) * K + k0 + tx] = __float2half(t[tx][r]);
}

// ---------------- LayerNorm -> fp16 ----------------
__global__ __launch_bounds__(256) void ln_kernel(const float* __restrict__ x,
                                                 const float* __restrict__ g,
                                                 const float* __restrict__ b,
                                                 __half* __restrict__ oh)
{
    int row = blockIdx.x;
    int t = threadIdx.x;
    float4 v = ((const float4*)(x + (size_t)row * CEMB))[t];
    float s  = v.x + v.y + v.z + v.w;
    float ss = v.x*v.x + v.y*v.y + v.z*v.z + v.w*v.w;
    #pragma unroll
    for (int o = 16; o > 0; o >>= 1) {
        s  += __shfl_xor_sync(0xffffffffu, s,  o);
        ss += __shfl_xor_sync(0xffffffffu, ss, o);
    }
    __shared__ float red[16];
    int warp = t >> 5, lane = t & 31;
    if (lane == 0) { red[warp] = s; red[warp + 8] = ss; }
    __syncthreads();
    float sum = 0.f, sumsq = 0.f;
    #pragma unroll
    for (int w = 0; w < 8; w++) { sum += red[w]; sumsq += red[w + 8]; }
    float mu   = sum * (1.0f / CEMB);
    float var  = sumsq * (1.0f / CEMB) - mu * mu;
    float rstd = rsqrtf(var + 1e-5f);
    float4 gv = ((const float4*)g)[t];
    float4 bv = ((const float4*)b)[t];
    H4 o;
    o.h[0] = __float2half((v.x - mu) * rstd * gv.x + bv.x);
    o.h[1] = __float2half((v.y - mu) * rstd * gv.y + bv.y);
    o.h[2] = __float2half((v.z - mu) * rstd * gv.z + bv.z);
    o.h[3] = __float2half((v.w - mu) * rstd * gv.w + bv.w);
    *(uint2*)(oh + (size_t)row * CEMB + t * 4) = o.u;
}

// ---------------- HMMA fp16 GEMM: C = A @ B^T + bias (R6 champion config) ----------------
// 128x128 tile, 8 warps (4m x 2n), warp tile 32x64, 2-stage, occ 2.
// EPI: 1 = fp32 out + residual, 2 = gelu -> fp16, 4 = fp16 out w/ q-scale (QKV)
#define STAGE_BYTES 32768
#define SMEM_GEMM (2 * STAGE_BYTES + 1024)

template<int EPI>
__global__ __launch_bounds__(GT, 2) void gemm_f16(
    const __half* __restrict__ Ah,
    const __half* __restrict__ Bf,
    const float* __restrict__ bias, const float* __restrict__ R,
    float* __restrict__ Cf, __half* __restrict__ Ch,
    int M, int N, int K)
{
    extern __shared__ char dsm[];
    uintptr_t pa = ((uintptr_t)dsm + 1023) & ~(uintptr_t)1023;
    uint32_t sb = smem_u32((char*)pa);

    int tid = threadIdx.x;
    int wid = tid >> 5, lid = tid & 31;
    int wm = wid >> 1, wn = wid & 1;
    int m0 = blockIdx.y * BM, n0 = blockIdx.x * BN;

    const int NC = K / BKE;
    int lrow = tid >> 3;
    int lch  = tid & 7;

    auto load_stage = [&](int c) {
        int buf = c & 1;
        uint32_t st = sb + buf * STAGE_BYTES;
        int k0 = c * BKE;
        #pragma unroll
        for (int t = 0; t < 4; t++) {
            int row = lrow + t * 32;
            uint32_t so = sw128((uint32_t)(row * 128 + lch * 16));
            size_t ga = (size_t)(m0 + row) * K + k0 + lch * 8;
            CP_ASYNC16(st + so,         (const char*)(Ah + ga));
            size_t gb = (size_t)(n0 + row) * K + k0 + lch * 8;
            CP_ASYNC16(st + 16384 + so, (const char*)(Bf + gb));
        }
    };

    float acc[2][8][4];
    #pragma unroll
    for (int mi = 0; mi < 2; mi++)
        #pragma unroll
        for (int j = 0; j < 8; j++)
            #pragma unroll
            for (int q = 0; q < 4; q++) acc[mi][j][q] = 0.f;

    int lrow16 = lid & 15;
    int khalf  = lid >> 4;

    load_stage(0);
    CP_COMMIT();

    for (int c = 0; c < NC; c++) {
        if (c + 1 < NC) { load_stage(c + 1); CP_COMMIT(); CP_WAIT1(); }
        else            { CP_WAIT0(); }
        __syncthreads();

        uint32_t st = sb + (c & 1) * STAGE_BYTES;

        #pragma unroll
        for (int s = 0; s < 4; s++) {
            uint32_t aH[2][4], bH[4][4];
            #pragma unroll
            for (int mi = 0; mi < 2; mi++) {
                int row = wm * 32 + mi * 16 + lrow16;
                int ch = (s * 2 + khalf) ^ (row & 7);
                uint32_t ad = st + (uint32_t)(row * 128 + ch * 16);
                LDSM_X4(aH[mi][0], aH[mi][1], aH[mi][2], aH[mi][3], ad);
            }
            #pragma unroll
            for (int nb = 0; nb < 4; nb++) {
                int row = wn * 64 + nb * 16 + lrow16;
                int ch = (s * 2 + khalf) ^ (row & 7);
                uint32_t bd = st + 16384 + (uint32_t)(row * 128 + ch * 16);
                LDSM_X4(bH[nb][0], bH[nb][1], bH[nb][2], bH[nb][3], bd);
            }
            #pragma unroll
            for (int mi = 0; mi < 2; mi++) {
                #pragma unroll
                for (int nb = 0; nb < 4; nb++) {
                    MMAF16(acc[mi][nb*2],   aH[mi], bH[nb][0], bH[nb][2]);
                    MMAF16(acc[mi][nb*2+1], aH[mi], bH[nb][1], bH[nb][3]);
                }
            }
        }
        __syncthreads();
    }

    int gid = lid >> 2, tig = lid & 3;
    #pragma unroll
    for (int mi = 0; mi < 2; mi++) {
        #pragma unroll
        for (int j = 0; j < 8; j++) {
            int r0 = m0 + wm * 32 + mi * 16 + gid;
            int r1 = r0 + 8;
            int col = n0 + wn * 64 + j * 8 + tig * 2;
            float b0 = bias[col], b1 = bias[col + 1];
            float v0 = acc[mi][j][0] + b0, v1 = acc[mi][j][1] + b1;
            float v2 = acc[mi][j][2] + b0, v3 = acc[mi][j][3] + b1;
            if (EPI == 1) {
                float2 q0 = *(const float2*)(R + (size_t)r0 * N + col);
                float2 q1 = *(const float2*)(R + (size_t)r1 * N + col);
                v0 += q0.x; v1 += q0.y; v2 += q1.x; v3 += q1.y;
            }
            if (EPI == 2) {
                v0 = gelu_f(v0); v1 = gelu_f(v1); v2 = gelu_f(v2); v3 = gelu_f(v3);
            }
            if (EPI == 4) {
                float sc = (col < CEMB) ? 0.125f : 1.0f;   // pre-scale q columns
                v0 *= sc; v1 *= sc; v2 *= sc; v3 *= sc;
            }
            if (EPI == 2 || EPI == 4) {
                H2 h0, h1;
                h0.h[0] = __float2half(v0); h0.h[1] = __float2half(v1);
                h1.h[0] = __float2half(v2); h1.h[1] = __float2half(v3);
                *(uint32_t*)(Ch + (size_t)r0 * N + col) = h0.u;
                *(uint32_t*)(Ch + (size_t)r1 * N + col) = h1.u;
            } else {
                *(float2*)(Cf + (size_t)r0 * N + col) = make_float2(v0, v1);
                *(float2*)(Cf + (size_t)r1 * N + col) = make_float2(v2, v3);
            }
        }
    }
}

// ---------------- HMMA flash attention: reads qkv directly, V via ldmatrix.trans ----------------
// smem: Q 16K @0 | buf(b) @16K+16K*b: K 8K, V 8K | P 16K @48K = 64KB, occ 2
#define ATSM_BUF(b) (16384 + (b) * 16384)
#define ATSM_P 49152
#define ATT_SMEM (65536 + 1024)

__global__ __launch_bounds__(256, 2) void attn_mma_kernel(
    const __half* __restrict__ qkv,
    __half* __restrict__ yo)
{
    extern __shared__ char dsm[];
    uintptr_t pa = ((uintptr_t)dsm + 1023) & ~(uintptr_t)1023;
    uint32_t sb = smem_u32((char*)pa);

    int qt = gridDim.x - 1 - blockIdx.x;
    int q0 = qt * 128;
    int bh = blockIdx.y;
    int b = bh >> 4, hd = bh & 15;
    const __half* qbase = qkv + (size_t)b * TT * RS + hd * HS;   // q at +0, k at +CEMB, v at +2*CEMB

    int tid = threadIdx.x;
    int wid = tid >> 5, lid = tid & 31;
    int lrow16 = lid & 15, khalf = lid >> 4;
    int arow = wid * 16 + lrow16;
    // trans-load lane geometry for V (fragments identical to non-trans [n][k] load)
    int vrow_in = ((lid >> 4) << 3) + (lid & 7);   // t-row within 16
    int vhalf   = (lid >> 3) & 1;                  // d-chunk half

    auto load_kv = [&](int jb, int buf) {
        int j0 = jb * 64;
        uint32_t st = sb + ATSM_BUF(buf);
        const __half* kf = qbase + CEMB;
        const __half* vf = qbase + 2 * CEMB;
        #pragma unroll
        for (int i = tid; i < 512; i += 256) {
            int row = i >> 3, ch = i & 7;
            uint32_t so = sw128((uint32_t)(row * 128 + ch * 16));
            size_t go = (size_t)(j0 + row) * RS + ch * 8;
            CP_ASYNC16(st + so,        (const char*)(kf + go));
            CP_ASYNC16(st + 8192 + so, (const char*)(vf + go));
        }
    };

    {
        #pragma unroll
        for (int i = tid; i < 1024; i += 256) {
            int row = i >> 3, ch = i & 7;
            uint32_t so = sw128((uint32_t)(row * 128 + ch * 16));
            CP_ASYNC16(sb + so, (const char*)(qbase + (size_t)(q0 + row) * RS + ch * 8));
        }
    }
    load_kv(0, 0);
    CP_COMMIT();

    float m_[2] = {-INFINITY, -INFINITY};
    float l_[2] = {0.f, 0.f};
    float acc[8][4];
    #pragma unroll
    for (int nb = 0; nb < 8; nb++)
        #pragma unroll
        for (int q = 0; q < 4; q++) acc[nb][q] = 0.f;

    int jbmax = q0 / 64 + 1;
    for (int jb = 0; jb <= jbmax; jb++) {
        int buf = jb & 1;
        CP_WAIT0();
        __syncthreads();
        if (jb < jbmax) { load_kv(jb + 1, buf ^ 1); CP_COMMIT(); }

        uint32_t sK = sb + ATSM_BUF(buf);
        uint32_t sV = sK + 8192;

        float s[8][4];
        #pragma unroll
        for (int nb = 0; nb < 8; nb++)
            #pragma unroll
            for (int q = 0; q < 4; q++) s[nb][q] = 0.f;

        #pragma unroll
        for (int ks = 0; ks < 4; ks++) {
            int ach = (ks * 2 + khalf) ^ (arow & 7);
            uint32_t aa = sb + (uint32_t)(arow * 128 + ach * 16);
            uint32_t aH[4];
            LDSM_X4(aH[0], aH[1], aH[2], aH[3], aa);
            uint32_t bH[4][4];
            #pragma unroll
            for (int nb2 = 0; nb2 < 4; nb2++) {
                int br = nb2 * 16 + lrow16;
                int bch = (ks * 2 + khalf) ^ (br & 7);
                uint32_t ba = sK + (uint32_t)(br * 128 + bch * 16);
                LDSM_X4(bH[nb2][0], bH[nb2][1], bH[nb2][2], bH[nb2][3], ba);
            }
            #pragma unroll
            for (int nb2 = 0; nb2 < 4; nb2++) {
                MMAF16(s[nb2*2],   aH, bH[nb2][0], bH[nb2][2]);
                MMAF16(s[nb2*2+1], aH, bH[nb2][1], bH[nb2][3]);
            }
        }

        int j0 = jb * 64;
        if (j0 + 63 > q0 + wid * 16) {
            int r0g = q0 + wid * 16 + (lid >> 2);
            #pragma unroll
            for (int nb = 0; nb < 8; nb++) {
                int c0 = j0 + nb * 8 + (lid & 3) * 2;
                if (c0     > r0g)     s[nb][0] = -INFINITY;
                if (c0 + 1 > r0g)     s[nb][1] = -INFINITY;
                if (c0     > r0g + 8) s[nb][2] = -INFINITY;
                if (c0 + 1 > r0g + 8) s[nb][3] = -INFINITY;
            }
        }

        float rmax[2] = {-INFINITY, -INFINITY};
        #pragma unroll
        for (int nb = 0; nb < 8; nb++) {
            rmax[0] = fmaxf(rmax[0], fmaxf(s[nb][0], s[nb][1]));
            rmax[1] = fmaxf(rmax[1], fmaxf(s[nb][2], s[nb][3]));
        }
        #pragma unroll
        for (int o = 1; o <= 2; o <<= 1) {
            rmax[0] = fmaxf(rmax[0], __shfl_xor_sync(0xffffffffu, rmax[0], o));
            rmax[1] = fmaxf(rmax[1], __shfl_xor_sync(0xffffffffu, rmax[1], o));
        }
        float mn0 = fmaxf(m_[0], rmax[0]);
        float mn1 = fmaxf(m_[1], rmax[1]);
        float alpha0 = __expf(m_[0] - mn0);
        float alpha1 = __expf(m_[1] - mn1);
        m_[0] = mn0; m_[1] = mn1;
        float rs[2] = {0.f, 0.f};
        #pragma unroll
        for (int nb = 0; nb < 8; nb++) {
            s[nb][0] = __expf(s[nb][0] - mn0); rs[0] += s[nb][0];
            s[nb][1] = __expf(s[nb][1] - mn0); rs[0] += s[nb][1];
            s[nb][2] = __expf(s[nb][2] - mn1); rs[1] += s[nb][2];
            s[nb][3] = __expf(s[nb][3] - mn1); rs[1] += s[nb][3];
        }
        #pragma unroll
        for (int o = 1; o <= 2; o <<= 1) {
            rs[0] += __shfl_xor_sync(0xffffffffu, rs[0], o);
            rs[1] += __shfl_xor_sync(0xffffffffu, rs[1], o);
        }
        l_[0] = l_[0] * alpha0 + rs[0];
        l_[1] = l_[1] * alpha1 + rs[1];
        #pragma unroll
        for (int nb = 0; nb < 8; nb++) {
            acc[nb][0] *= alpha0; acc[nb][1] *= alpha0;
            acc[nb][2] *= alpha1; acc[nb][3] *= alpha1;
        }

        {
            int r0 = wid * 16 + (lid >> 2);
            #pragma unroll
            for (int nb = 0; nb < 8; nb++) {
                int coff = (nb * 8 + (lid & 3) * 2) * 2;
                uint32_t o0 = sw128((uint32_t)(r0 * 128 + coff));
                uint32_t o1 = sw128((uint32_t)((r0 + 8) * 128 + coff));
                H2 h;
                h.h[0] = __float2half(s[nb][0]); h.h[1] = __float2half(s[nb][1]);
                STS32(sb + ATSM_P + o0, h.u);
                h.h[0] = __float2half(s[nb][2]); h.h[1] = __float2half(s[nb][3]);
                STS32(sb + ATSM_P + o1, h.u);
            }
        }
        __syncwarp();

        // O += P @ V, V fragments via trans ldmatrix directly from [t][d] tile
        #pragma unroll
        for (int ks = 0; ks < 4; ks++) {
            int ach = (ks * 2 + khalf) ^ (arow & 7);
            uint32_t paddr = sb + ATSM_P + (uint32_t)(arow * 128 + ach * 16);
            uint32_t pH[4];
            LDSM_X4(pH[0], pH[1], pH[2], pH[3], paddr);
            uint32_t bH[4][4];
            int trow = ks * 16 + vrow_in;
            #pragma unroll
            for (int nb2 = 0; nb2 < 4; nb2++) {
                int chunk = nb2 * 2 + vhalf;
                uint32_t ba = sV + (uint32_t)(trow * 128 + ((chunk ^ (trow & 7)) * 16));
                LDSM_X4_T(bH[nb2][0], bH[nb2][1], bH[nb2][2], bH[nb2][3], ba);
            }
            #pragma unroll
            for (int nb2 = 0; nb2 < 4; nb2++) {
                MMAF16(acc[nb2*2],   pH, bH[nb2][0], bH[nb2][2]);
                MMAF16(acc[nb2*2+1], pH, bH[nb2][1], bH[nb2][3]);
            }
        }
    }

    float inv0 = 1.0f / l_[0];
    float inv1 = 1.0f / l_[1];
    size_t r0g = (size_t)b * TT + q0 + wid * 16 + (lid >> 2);
    #pragma unroll
    for (int nb = 0; nb < 8; nb++) {
        int col = hd * HS + nb * 8 + (lid & 3) * 2;
        H2 h;
        h.h[0] = __float2half(acc[nb][0] * inv0);
        h.h[1] = __float2half(acc[nb][1] * inv0);
        *(uint32_t*)(yo + r0g * CEMB + col) = h.u;
        h.h[0] = __float2half(acc[nb][2] * inv1);
        h.h[1] = __float2half(acc[nb][3] * inv1);
        *(uint32_t*)(yo + (r0g + 8) * CEMB + col) = h.u;
    }
}

// ---------------- launch ----------------
extern "C" void kernel_launch(void* const* d_in, const int* in_sizes, int n_in,
                              void* d_out, int out_size)
{
    const float* x      = (const float*)d_in[0];
    const float* ln1_g  = (const float*)d_in[1];
    const float* ln1_b  = (const float*)d_in[2];
    const float* w_attn = (const float*)d_in[3];
    const float* b_attn = (const float*)d_in[4];
    const float* w_proj = (const float*)d_in[5];
    const float* b_proj = (const float*)d_in[6];
    const float* ln2_g  = (const float*)d_in[7];
    const float* ln2_b  = (const float*)d_in[8];
    const float* w_fc   = (const float*)d_in[9];
    const float* b_fc   = (const float*)d_in[10];
    const float* w_fc2  = (const float*)d_in[11];
    const float* b_fc2  = (const float*)d_in[12];
    float* out = (float*)d_out;

    float *x2;
    __half *qkv, *h, *y, *f;
    __half *wa, *wp, *wf, *w2;
    cudaGetSymbolAddress((void**)&qkv, g_qkv);
    cudaGetSymbolAddress((void**)&x2,  g_x2);
    cudaGetSymbolAddress((void**)&h,   g_h);
    cudaGetSymbolAddress((void**)&y,   g_y);
    cudaGetSymbolAddress((void**)&f,   g_f);
    cudaGetSymbolAddress((void**)&wa,  g_wa);
    cudaGetSymbolAddress((void**)&wp,  g_wp);
    cudaGetSymbolAddress((void**)&wf,  g_wf);
    cudaGetSymbolAddress((void**)&w2,  g_w2);

    cudaFuncSetAttribute(gemm_f16<1>, cudaFuncAttributeMaxDynamicSharedMemorySize, SMEM_GEMM);
    cudaFuncSetAttribute(gemm_f16<2>, cudaFuncAttributeMaxDynamicSharedMemorySize, SMEM_GEMM);
    cudaFuncSetAttribute(gemm_f16<4>, cudaFuncAttributeMaxDynamicSharedMemorySize, SMEM_GEMM);
    cudaFuncSetAttribute(attn_mma_kernel, cudaFuncAttributeMaxDynamicSharedMemorySize, ATT_SMEM);

    dim3 blk(256);

    wconv_kernel<<<dim3(3*CEMB/32, CEMB/32), blk>>>(w_attn, wa, CEMB, 3*CEMB);
    wconv_kernel<<<dim3(CEMB/32,   CEMB/32), blk>>>(w_proj, wp, CEMB, CEMB);
    wconv_kernel<<<dim3(DFF/32,    CEMB/32), blk>>>(w_fc,   wf, CEMB, DFF);
    wconv_kernel<<<dim3(CEMB/32,   DFF/32),  blk>>>(w_fc2,  w2, DFF,  CEMB);

    ln_kernel<<<MROWS, blk>>>(x, ln1_g, ln1_b, h);
    // qkv fp16 out, q columns pre-scaled by 0.125
    gemm_f16<4><<<dim3(3*CEMB/BN, MROWS/BM), GT, SMEM_GEMM>>>(
        h, wa, b_attn, nullptr, nullptr, qkv, MROWS, 3*CEMB, CEMB);
    attn_mma_kernel<<<dim3(TT/128, BB*NHEADS), blk, ATT_SMEM>>>(qkv, y);
    gemm_f16<1><<<dim3(CEMB/BN, MROWS/BM), GT, SMEM_GEMM>>>(
        y, wp, b_proj, x, x2, nullptr, MROWS, CEMB, CEMB);
    ln_kernel<<<MROWS, blk>>>(x2, ln2_g, ln2_b, h);
    gemm_f16<2><<<dim3(DFF/BN, MROWS/BM), GT, SMEM_GEMM>>>(
        h, wf, b_fc, nullptr, nullptr, f, MROWS, DFF, CEMB);
    gemm_f16<1><<<dim3(CEMB/BN, MROWS/BM), GT, SMEM_GEMM>>>(
        f, w2, b_fc2, x2, out, nullptr, MROWS, CEMB, DFF);
}

// round 11
// speedup vs baseline: 1.1427x; 1.0218x over previous
#include <cuda_runtime.h>
#include <cuda_fp16.h>
#include <math.h>
#include <stdint.h>

#define CEMB 1024
#define NHEADS 16
#define HS 64
#define DFF 4096
#define BB 4
#define TT 2048
#define MROWS (BB*TT)   // 8192
#define RS (3*CEMB)     // qkv row stride (elements)

#define BM 128
#define BN 128
#define BKE 64
#define GT 256

// ---------------- scratch ----------------
__device__ __half g_qkv[(size_t)MROWS * 3 * CEMB];  // fp16 qkv, q pre-scaled 0.125
__device__ float g_x2 [(size_t)MROWS * CEMB];
__device__ __half g_h [(size_t)MROWS * CEMB];       // ln out
__device__ __half g_y [(size_t)MROWS * CEMB];       // attn out
__device__ __half g_f [(size_t)MROWS * DFF];        // mlp hidden
// weights, transposed to [N,K] K-major, fp16
__device__ __half g_wa[(size_t)3*CEMB * CEMB];
__device__ __half g_wp[(size_t)CEMB * CEMB];
__device__ __half g_wf[(size_t)DFF * CEMB];
__device__ __half g_w2[(size_t)CEMB * DFF];

// ---------------- PTX helpers ----------------
__device__ __forceinline__ uint32_t smem_u32(const void* p) {
    uint32_t a;
    asm("{ .reg .u64 t; cvta.to.shared.u64 t, %1; cvt.u32.u64 %0, t; }" : "=r"(a) : "l"(p));
    return a;
}
#define CP_ASYNC16(s, g) \
    asm volatile("cp.async.cg.shared.global [%0], [%1], 16;" :: "r"(s), "l"(g) : "memory")
#define CP_COMMIT() asm volatile("cp.async.commit_group;" ::: "memory")
#define CP_WAIT1()  asm volatile("cp.async.wait_group 1;" ::: "memory")
#define CP_WAIT0()  asm volatile("cp.async.wait_group 0;" ::: "memory")
#define LDSM_X4(r0, r1, r2, r3, addr) \
    asm volatile("ldmatrix.sync.aligned.m8n8.x4.shared.b16 {%0,%1,%2,%3}, [%4];" \
        : "=r"(r0), "=r"(r1), "=r"(r2), "=r"(r3) : "r"(addr))
#define LDSM_X4_T(r0, r1, r2, r3, addr) \
    asm volatile("ldmatrix.sync.aligned.m8n8.x4.trans.shared.b16 {%0,%1,%2,%3}, [%4];" \
        : "=r"(r0), "=r"(r1), "=r"(r2), "=r"(r3) : "r"(addr))
#define MMAF16(c, a, b0v, b1v) \
    asm volatile("mma.sync.aligned.m16n8k16.row.col.f32.f16.f16.f32 " \
        "{%0,%1,%2,%3}, {%4,%5,%6,%7}, {%8,%9}, {%0,%1,%2,%3};" \
        : "+f"((c)[0]), "+f"((c)[1]), "+f"((c)[2]), "+f"((c)[3]) \
        : "r"((a)[0]), "r"((a)[1]), "r"((a)[2]), "r"((a)[3]), "r"(b0v), "r"(b1v))

__device__ __forceinline__ uint32_t sw128(uint32_t off) { return off ^ ((off >> 3) & 0x70); }

__device__ __forceinline__ float gelu_f(float x) {
    float t = tanhf(0.79788456080286536f * (x + 0.044715f * x * x * x));
    return 0.5f * x * (1.0f + t);
}

union H4 { __half h[4]; uint2 u; };
union H2 { __half h[2]; uint32_t u; };

// ---------------- weight transpose + fp16 convert ----------------
__global__ __launch_bounds__(256) void wconv_kernel(const float* __restrict__ W,
    __half* __restrict__ Wf, int K, int N)
{
    __shared__ float t[32][33];
    int n0 = blockIdx.x * 32, k0 = blockIdx.y * 32;
    int tx = threadIdx.x & 31, ty = threadIdx.x >> 5;
    #pragma unroll
    for (int r = ty; r < 32; r += 8)
        t[r][tx] = W[(size_t)(k0 + r) * N + n0 + tx];
    __syncthreads();
    #pragma unroll
    for (int r = ty; r < 32; r += 8)
        Wf[(size_t)(n0 + r) * K + k0 + tx] = __float2half(t[tx][r]);
}

// ---------------- LayerNorm -> fp16 ----------------
__global__ __launch_bounds__(256) void ln_kernel(const float* __restrict__ x,
                                                 const float* __restrict__ g,
                                                 const float* __restrict__ b,
                                                 __half* __restrict__ oh)
{
    int row = blockIdx.x;
    int t = threadIdx.x;
    float4 v = ((const float4*)(x + (size_t)row * CEMB))[t];
    float s  = v.x + v.y + v.z + v.w;
    float ss = v.x*v.x + v.y*v.y + v.z*v.z + v.w*v.w;
    #pragma unroll
    for (int o = 16; o > 0; o >>= 1) {
        s  += __shfl_xor_sync(0xffffffffu, s,  o);
        ss += __shfl_xor_sync(0xffffffffu, ss, o);
    }
    __shared__ float red[16];
    int warp = t >> 5, lane = t & 31;
    if (lane == 0) { red[warp] = s; red[warp + 8] = ss; }
    __syncthreads();
    float sum = 0.f, sumsq = 0.f;
    #pragma unroll
    for (int w = 0; w < 8; w++) { sum += red[w]; sumsq += red[w + 8]; }
    float mu   = sum * (1.0f / CEMB);
    float var  = sumsq * (1.0f / CEMB) - mu * mu;
    float rstd = rsqrtf(var + 1e-5f);
    float4 gv = ((const float4*)g)[t];
    float4 bv = ((const float4*)b)[t];
    H4 o;
    o.h[0] = __float2half((v.x - mu) * rstd * gv.x + bv.x);
    o.h[1] = __float2half((v.y - mu) * rstd * gv.y + bv.y);
    o.h[2] = __float2half((v.z - mu) * rstd * gv.z + bv.z);
    o.h[3] = __float2half((v.w - mu) * rstd * gv.w + bv.w);
    *(uint2*)(oh + (size_t)row * CEMB + t * 4) = o.u;
}

// ---------------- HMMA fp16 GEMM: C = A @ B^T + bias (R6 champion config) ----------------
// 128x128 tile, 8 warps (4m x 2n), warp tile 32x64, 2-stage, occ 2.
// EPI: 1 = fp32 out + residual, 2 = gelu -> fp16, 4 = fp16 out w/ q-scale (QKV)
#define STAGE_BYTES 32768
#define SMEM_GEMM (2 * STAGE_BYTES + 1024)

template<int EPI>
__global__ __launch_bounds__(GT, 2) void gemm_f16(
    const __half* __restrict__ Ah,
    const __half* __restrict__ Bf,
    const float* __restrict__ bias, const float* __restrict__ R,
    float* __restrict__ Cf, __half* __restrict__ Ch,
    int M, int N, int K)
{
    extern __shared__ char dsm[];
    uintptr_t pa = ((uintptr_t)dsm + 1023) & ~(uintptr_t)1023;
    uint32_t sb = smem_u32((char*)pa);

    int tid = threadIdx.x;
    int wid = tid >> 5, lid = tid & 31;
    int wm = wid >> 1, wn = wid & 1;
    int m0 = blockIdx.y * BM, n0 = blockIdx.x * BN;

    const int NC = K / BKE;
    int lrow = tid >> 3;
    int lch  = tid & 7;

    auto load_stage = [&](int c) {
        int buf = c & 1;
        uint32_t st = sb + buf * STAGE_BYTES;
        int k0 = c * BKE;
        #pragma unroll
        for (int t = 0; t < 4; t++) {
            int row = lrow + t * 32;
            uint32_t so = sw128((uint32_t)(row * 128 + lch * 16));
            size_t ga = (size_t)(m0 + row) * K + k0 + lch * 8;
            CP_ASYNC16(st + so,         (const char*)(Ah + ga));
            size_t gb = (size_t)(n0 + row) * K + k0 + lch * 8;
            CP_ASYNC16(st + 16384 + so, (const char*)(Bf + gb));
        }
    };

    float acc[2][8][4];
    #pragma unroll
    for (int mi = 0; mi < 2; mi++)
        #pragma unroll
        for (int j = 0; j < 8; j++)
            #pragma unroll
            for (int q = 0; q < 4; q++) acc[mi][j][q] = 0.f;

    int lrow16 = lid & 15;
    int khalf  = lid >> 4;

    load_stage(0);
    CP_COMMIT();

    for (int c = 0; c < NC; c++) {
        if (c + 1 < NC) { load_stage(c + 1); CP_COMMIT(); CP_WAIT1(); }
        else            { CP_WAIT0(); }
        __syncthreads();

        uint32_t st = sb + (c & 1) * STAGE_BYTES;

        #pragma unroll
        for (int s = 0; s < 4; s++) {
            uint32_t aH[2][4], bH[4][4];
            #pragma unroll
            for (int mi = 0; mi < 2; mi++) {
                int row = wm * 32 + mi * 16 + lrow16;
                int ch = (s * 2 + khalf) ^ (row & 7);
                uint32_t ad = st + (uint32_t)(row * 128 + ch * 16);
                LDSM_X4(aH[mi][0], aH[mi][1], aH[mi][2], aH[mi][3], ad);
            }
            #pragma unroll
            for (int nb = 0; nb < 4; nb++) {
                int row = wn * 64 + nb * 16 + lrow16;
                int ch = (s * 2 + khalf) ^ (row & 7);
                uint32_t bd = st + 16384 + (uint32_t)(row * 128 + ch * 16);
                LDSM_X4(bH[nb][0], bH[nb][1], bH[nb][2], bH[nb][3], bd);
            }
            #pragma unroll
            for (int mi = 0; mi < 2; mi++) {
                #pragma unroll
                for (int nb = 0; nb < 4; nb++) {
                    MMAF16(acc[mi][nb*2],   aH[mi], bH[nb][0], bH[nb][2]);
                    MMAF16(acc[mi][nb*2+1], aH[mi], bH[nb][1], bH[nb][3]);
                }
            }
        }
        __syncthreads();
    }

    int gid = lid >> 2, tig = lid & 3;
    #pragma unroll
    for (int mi = 0; mi < 2; mi++) {
        #pragma unroll
        for (int j = 0; j < 8; j++) {
            int r0 = m0 + wm * 32 + mi * 16 + gid;
            int r1 = r0 + 8;
            int col = n0 + wn * 64 + j * 8 + tig * 2;
            float b0 = bias[col], b1 = bias[col + 1];
            float v0 = acc[mi][j][0] + b0, v1 = acc[mi][j][1] + b1;
            float v2 = acc[mi][j][2] + b0, v3 = acc[mi][j][3] + b1;
            if (EPI == 1) {
                float2 q0 = *(const float2*)(R + (size_t)r0 * N + col);
                float2 q1 = *(const float2*)(R + (size_t)r1 * N + col);
                v0 += q0.x; v1 += q0.y; v2 += q1.x; v3 += q1.y;
            }
            if (EPI == 2) {
                v0 = gelu_f(v0); v1 = gelu_f(v1); v2 = gelu_f(v2); v3 = gelu_f(v3);
            }
            if (EPI == 4) {
                float sc = (col < CEMB) ? 0.125f : 1.0f;   // pre-scale q columns
                v0 *= sc; v1 *= sc; v2 *= sc; v3 *= sc;
            }
            if (EPI == 2 || EPI == 4) {
                H2 h0, h1;
                h0.h[0] = __float2half(v0); h0.h[1] = __float2half(v1);
                h1.h[0] = __float2half(v2); h1.h[1] = __float2half(v3);
                *(uint32_t*)(Ch + (size_t)r0 * N + col) = h0.u;
                *(uint32_t*)(Ch + (size_t)r1 * N + col) = h1.u;
            } else {
                *(float2*)(Cf + (size_t)r0 * N + col) = make_float2(v0, v1);
                *(float2*)(Cf + (size_t)r1 * N + col) = make_float2(v2, v3);
            }
        }
    }
}

// ---------------- HMMA flash attention: P kept in registers (FA2), V via trans-LDSM ----------------
// smem: Q 16K @0 | buf(b) @16K+16K*b: K 8K, V 8K = 48KB, occ 2
#define ATSM_BUF(b) (16384 + (b) * 16384)
#define ATT_SMEM (49152 + 1024)

__global__ __launch_bounds__(256, 2) void attn_mma_kernel(
    const __half* __restrict__ qkv,
    __half* __restrict__ yo)
{
    extern __shared__ char dsm[];
    uintptr_t pa = ((uintptr_t)dsm + 1023) & ~(uintptr_t)1023;
    uint32_t sb = smem_u32((char*)pa);

    int qt = gridDim.x - 1 - blockIdx.x;
    int q0 = qt * 128;
    int bh = blockIdx.y;
    int b = bh >> 4, hd = bh & 15;
    const __half* qbase = qkv + (size_t)b * TT * RS + hd * HS;   // q at +0, k at +CEMB, v at +2*CEMB

    int tid = threadIdx.x;
    int wid = tid >> 5, lid = tid & 31;
    int lrow16 = lid & 15, khalf = lid >> 4;
    int arow = wid * 16 + lrow16;
    // trans-load lane geometry for V
    int vrow_in = ((lid >> 4) << 3) + (lid & 7);   // t-row within 16
    int vhalf   = (lid >> 3) & 1;                  // d-chunk half

    auto load_kv = [&](int jb, int buf) {
        int j0 = jb * 64;
        uint32_t st = sb + ATSM_BUF(buf);
        const __half* kf = qbase + CEMB;
        const __half* vf = qbase + 2 * CEMB;
        #pragma unroll
        for (int i = tid; i < 512; i += 256) {
            int row = i >> 3, ch = i & 7;
            uint32_t so = sw128((uint32_t)(row * 128 + ch * 16));
            size_t go = (size_t)(j0 + row) * RS + ch * 8;
            CP_ASYNC16(st + so,        (const char*)(kf + go));
            CP_ASYNC16(st + 8192 + so, (const char*)(vf + go));
        }
    };

    {
        #pragma unroll
        for (int i = tid; i < 1024; i += 256) {
            int row = i >> 3, ch = i & 7;
            uint32_t so = sw128((uint32_t)(row * 128 + ch * 16));
            CP_ASYNC16(sb + so, (const char*)(qbase + (size_t)(q0 + row) * RS + ch * 8));
        }
    }
    load_kv(0, 0);
    CP_COMMIT();

    float m_[2] = {-INFINITY, -INFINITY};
    float l_[2] = {0.f, 0.f};
    float acc[8][4];
    #pragma unroll
    for (int nb = 0; nb < 8; nb++)
        #pragma unroll
        for (int q = 0; q < 4; q++) acc[nb][q] = 0.f;

    int jbmax = q0 / 64 + 1;
    for (int jb = 0; jb <= jbmax; jb++) {
        int buf = jb & 1;
        CP_WAIT0();
        __syncthreads();
        if (jb < jbmax) { load_kv(jb + 1, buf ^ 1); CP_COMMIT(); }

        uint32_t sK = sb + ATSM_BUF(buf);
        uint32_t sV = sK + 8192;

        float s[8][4];
        #pragma unroll
        for (int nb = 0; nb < 8; nb++)
            #pragma unroll
            for (int q = 0; q < 4; q++) s[nb][q] = 0.f;

        #pragma unroll
        for (int ks = 0; ks < 4; ks++) {
            int ach = (ks * 2 + khalf) ^ (arow & 7);
            uint32_t aa = sb + (uint32_t)(arow * 128 + ach * 16);
            uint32_t aH[4];
            LDSM_X4(aH[0], aH[1], aH[2], aH[3], aa);
            uint32_t bH[4][4];
            #pragma unroll
            for (int nb2 = 0; nb2 < 4; nb2++) {
                int br = nb2 * 16 + lrow16;
                int bch = (ks * 2 + khalf) ^ (br & 7);
                uint32_t ba = sK + (uint32_t)(br * 128 + bch * 16);
                LDSM_X4(bH[nb2][0], bH[nb2][1], bH[nb2][2], bH[nb2][3], ba);
            }
            #pragma unroll
            for (int nb2 = 0; nb2 < 4; nb2++) {
                MMAF16(s[nb2*2],   aH, bH[nb2][0], bH[nb2][2]);
                MMAF16(s[nb2*2+1], aH, bH[nb2][1], bH[nb2][3]);
            }
        }

        int j0 = jb * 64;
        if (j0 + 63 > q0 + wid * 16) {
            int r0g = q0 + wid * 16 + (lid >> 2);
            #pragma unroll
            for (int nb = 0; nb < 8; nb++) {
                int c0 = j0 + nb * 8 + (lid & 3) * 2;
                if (c0     > r0g)     s[nb][0] = -INFINITY;
                if (c0 + 1 > r0g)     s[nb][1] = -INFINITY;
                if (c0     > r0g + 8) s[nb][2] = -INFINITY;
                if (c0 + 1 > r0g + 8) s[nb][3] = -INFINITY;
            }
        }

        float rmax[2] = {-INFINITY, -INFINITY};
        #pragma unroll
        for (int nb = 0; nb < 8; nb++) {
            rmax[0] = fmaxf(rmax[0], fmaxf(s[nb][0], s[nb][1]));
            rmax[1] = fmaxf(rmax[1], fmaxf(s[nb][2], s[nb][3]));
        }
        #pragma unroll
        for (int o = 1; o <= 2; o <<= 1) {
            rmax[0] = fmaxf(rmax[0], __shfl_xor_sync(0xffffffffu, rmax[0], o));
            rmax[1] = fmaxf(rmax[1], __shfl_xor_sync(0xffffffffu, rmax[1], o));
        }
        float mn0 = fmaxf(m_[0], rmax[0]);
        float mn1 = fmaxf(m_[1], rmax[1]);
        float alpha0 = __expf(m_[0] - mn0);
        float alpha1 = __expf(m_[1] - mn1);
        m_[0] = mn0; m_[1] = mn1;
        float rs[2] = {0.f, 0.f};
        #pragma unroll
        for (int nb = 0; nb < 8; nb++) {
            s[nb][0] = __expf(s[nb][0] - mn0); rs[0] += s[nb][0];
            s[nb][1] = __expf(s[nb][1] - mn0); rs[0] += s[nb][1];
            s[nb][2] = __expf(s[nb][2] - mn1); rs[1] += s[nb][2];
            s[nb][3] = __expf(s[nb][3] - mn1); rs[1] += s[nb][3];
        }
        #pragma unroll
        for (int o = 1; o <= 2; o <<= 1) {
            rs[0] += __shfl_xor_sync(0xffffffffu, rs[0], o);
            rs[1] += __shfl_xor_sync(0xffffffffu, rs[1], o);
        }
        l_[0] = l_[0] * alpha0 + rs[0];
        l_[1] = l_[1] * alpha1 + rs[1];
        #pragma unroll
        for (int nb = 0; nb < 8; nb++) {
            acc[nb][0] *= alpha0; acc[nb][1] *= alpha0;
            acc[nb][2] *= alpha1; acc[nb][3] *= alpha1;
        }

        // ---- convert P to fp16 A-fragments in registers (no smem round trip) ----
        // S C-frag (m16n8) of adjacent nb pair == A-frag (m16k16) for k-chunk ks:
        //   R0={s[2ks][0],s[2ks][1]} R1={s[2ks][2],s[2ks][3]}
        //   R2={s[2ks+1][0],s[2ks+1][1]} R3={s[2ks+1][2],s[2ks+1][3]}
        uint32_t pH[4][4];
        #pragma unroll
        for (int ks = 0; ks < 4; ks++) {
            H2 t0, t1, t2, t3;
            t0.h[0] = __float2half(s[2*ks][0]);   t0.h[1] = __float2half(s[2*ks][1]);
            t1.h[0] = __float2half(s[2*ks][2]);   t1.h[1] = __float2half(s[2*ks][3]);
            t2.h[0] = __float2half(s[2*ks+1][0]); t2.h[1] = __float2half(s[2*ks+1][1]);
            t3.h[0] = __float2half(s[2*ks+1][2]); t3.h[1] = __float2half(s[2*ks+1][3]);
            pH[ks][0] = t0.u; pH[ks][1] = t1.u; pH[ks][2] = t2.u; pH[ks][3] = t3.u;
        }

        // O += P @ V, V fragments via trans ldmatrix from [t][d] tile
        #pragma unroll
        for (int ks = 0; ks < 4; ks++) {
            uint32_t bH[4][4];
            int trow = ks * 16 + vrow_in;
            #pragma unroll
            for (int nb2 = 0; nb2 < 4; nb2++) {
                int chunk = nb2 * 2 + vhalf;
                uint32_t ba = sV + (uint32_t)(trow * 128 + ((chunk ^ (trow & 7)) * 16));
                LDSM_X4_T(bH[nb2][0], bH[nb2][1], bH[nb2][2], bH[nb2][3], ba);
            }
            #pragma unroll
            for (int nb2 = 0; nb2 < 4; nb2++) {
                MMAF16(acc[nb2*2],   pH[ks], bH[nb2][0], bH[nb2][2]);
                MMAF16(acc[nb2*2+1], pH[ks], bH[nb2][1], bH[nb2][3]);
            }
        }
    }

    float inv0 = 1.0f / l_[0];
    float inv1 = 1.0f / l_[1];
    size_t r0g = (size_t)b * TT + q0 + wid * 16 + (lid >> 2);
    #pragma unroll
    for (int nb = 0; nb < 8; nb++) {
        int col = hd * HS + nb * 8 + (lid & 3) * 2;
        H2 h;
        h.h[0] = __float2half(acc[nb][0] * inv0);
        h.h[1] = __float2half(acc[nb][1] * inv0);
        *(uint32_t*)(yo + r0g * CEMB + col) = h.u;
        h.h[0] = __float2half(acc[nb][2] * inv1);
        h.h[1] = __float2half(acc[nb][3] * inv1);
        *(uint32_t*)(yo + (r0g + 8) * CEMB + col) = h.u;
    }
}

// ---------------- launch ----------------
extern "C" void kernel_launch(void* const* d_in, const int* in_sizes, int n_in,
                              void* d_out, int out_size)
{
    const float* x      = (const float*)d_in[0];
    const float* ln1_g  = (const float*)d_in[1];
    const float* ln1_b  = (const float*)d_in[2];
    const float* w_attn = (const float*)d_in[3];
    const float* b_attn = (const float*)d_in[4];
    const float* w_proj = (const float*)d_in[5];
    const float* b_proj = (const float*)d_in[6];
    const float* ln2_g  = (const float*)d_in[7];
    const float* ln2_b  = (const float*)d_in[8];
    const float* w_fc   = (const float*)d_in[9];
    const float* b_fc   = (const float*)d_in[10];
    const float* w_fc2  = (const float*)d_in[11];
    const float* b_fc2  = (const float*)d_in[12];
    float* out = (float*)d_out;

    float *x2;
    __half *qkv, *h, *y, *f;
    __half *wa, *wp, *wf, *w2;
    cudaGetSymbolAddress((void**)&qkv, g_qkv);
    cudaGetSymbolAddress((void**)&x2,  g_x2);
    cudaGetSymbolAddress((void**)&h,   g_h);
    cudaGetSymbolAddress((void**)&y,   g_y);
    cudaGetSymbolAddress((void**)&f,   g_f);
    cudaGetSymbolAddress((void**)&wa,  g_wa);
    cudaGetSymbolAddress((void**)&wp,  g_wp);
    cudaGetSymbolAddress((void**)&wf,  g_wf);
    cudaGetSymbolAddress((void**)&w2,  g_w2);

    cudaFuncSetAttribute(gemm_f16<1>, cudaFuncAttributeMaxDynamicSharedMemorySize, SMEM_GEMM);
    cudaFuncSetAttribute(gemm_f16<2>, cudaFuncAttributeMaxDynamicSharedMemorySize, SMEM_GEMM);
    cudaFuncSetAttribute(gemm_f16<4>, cudaFuncAttributeMaxDynamicSharedMemorySize, SMEM_GEMM);
    cudaFuncSetAttribute(attn_mma_kernel, cudaFuncAttributeMaxDynamicSharedMemorySize, ATT_SMEM);

    dim3 blk(256);

    wconv_kernel<<<dim3(3*CEMB/32, CEMB/32), blk>>>(w_attn, wa, CEMB, 3*CEMB);
    wconv_kernel<<<dim3(CEMB/32,   CEMB/32), blk>>>(w_proj, wp, CEMB, CEMB);
    wconv_kernel<<<dim3(DFF/32,    CEMB/32), blk>>>(w_fc,   wf, CEMB, DFF);
    wconv_kernel<<<dim3(CEMB/32,   DFF/32),  blk>>>(w_fc2,  w2, DFF,  CEMB);

    ln_kernel<<<MROWS, blk>>>(x, ln1_g, ln1_b, h);
    // qkv fp16 out, q columns pre-scaled by 0.125
    gemm_f16<4><<<dim3(3*CEMB/BN, MROWS/BM), GT, SMEM_GEMM>>>(
        h, wa, b_attn, nullptr, nullptr, qkv, MROWS, 3*CEMB, CEMB);
    attn_mma_kernel<<<dim3(TT/128, BB*NHEADS), blk, ATT_SMEM>>>(qkv, y);
    gemm_f16<1><<<dim3(CEMB/BN, MROWS/BM), GT, SMEM_GEMM>>>(
        y, wp, b_proj, x, x2, nullptr, MROWS, CEMB, CEMB);
    ln_kernel<<<MROWS, blk>>>(x2, ln2_g, ln2_b, h);
    gemm_f16<2><<<dim3(DFF/BN, MROWS/BM), GT, SMEM_GEMM>>>(
        h, wf, b_fc, nullptr, nullptr, f, MROWS, DFF, CEMB);
    gemm_f16<1><<<dim3(CEMB/BN, MROWS/BM), GT, SMEM_GEMM>>>(
        f, w2, b_fc2, x2, out, nullptr, MROWS, CEMB, DFF);
}

// round 12
// speedup vs baseline: 1.1533x; 1.0093x over previous
#include <cuda_runtime.h>
#include <cuda_fp16.h>
#include <math.h>
#include <stdint.h>

#define CEMB 1024
#define NHEADS 16
#define HS 64
#define DFF 4096
#define BB 4
#define TT 2048
#define MROWS (BB*TT)   // 8192
#define RS (3*CEMB)     // qkv row stride (elements)

#define BM 128
#define BN 128
#define BKE 64
#define GT 256

// ---------------- scratch ----------------
__device__ __half g_qkv[(size_t)MROWS * 3 * CEMB];  // fp16 qkv, q pre-scaled 0.125
__device__ float g_x2 [(size_t)MROWS * CEMB];
__device__ __half g_h [(size_t)MROWS * CEMB];       // ln out
__device__ __half g_y [(size_t)MROWS * CEMB];       // attn out
__device__ __half g_f [(size_t)MROWS * DFF];        // mlp hidden
// weights, transposed to [N,K] K-major, fp16
__device__ __half g_wa[(size_t)3*CEMB * CEMB];
__device__ __half g_wp[(size_t)CEMB * CEMB];
__device__ __half g_wf[(size_t)DFF * CEMB];
__device__ __half g_w2[(size_t)CEMB * DFF];

// ---------------- PTX helpers ----------------
__device__ __forceinline__ uint32_t smem_u32(const void* p) {
    uint32_t a;
    asm("{ .reg .u64 t; cvta.to.shared.u64 t, %1; cvt.u32.u64 %0, t; }" : "=r"(a) : "l"(p));
    return a;
}
#define CP_ASYNC16(s, g) \
    asm volatile("cp.async.cg.shared.global [%0], [%1], 16;" :: "r"(s), "l"(g) : "memory")
#define CP_COMMIT() asm volatile("cp.async.commit_group;" ::: "memory")
#define CP_WAIT1()  asm volatile("cp.async.wait_group 1;" ::: "memory")
#define CP_WAIT0()  asm volatile("cp.async.wait_group 0;" ::: "memory")
#define LDSM_X4(r0, r1, r2, r3, addr) \
    asm volatile("ldmatrix.sync.aligned.m8n8.x4.shared.b16 {%0,%1,%2,%3}, [%4];" \
        : "=r"(r0), "=r"(r1), "=r"(r2), "=r"(r3) : "r"(addr))
#define LDSM_X4_T(r0, r1, r2, r3, addr) \
    asm volatile("ldmatrix.sync.aligned.m8n8.x4.trans.shared.b16 {%0,%1,%2,%3}, [%4];" \
        : "=r"(r0), "=r"(r1), "=r"(r2), "=r"(r3) : "r"(addr))
#define MMAF16(c, a, b0v, b1v) \
    asm volatile("mma.sync.aligned.m16n8k16.row.col.f32.f16.f16.f32 " \
        "{%0,%1,%2,%3}, {%4,%5,%6,%7}, {%8,%9}, {%0,%1,%2,%3};" \
        : "+f"((c)[0]), "+f"((c)[1]), "+f"((c)[2]), "+f"((c)[3]) \
        : "r"((a)[0]), "r"((a)[1]), "r"((a)[2]), "r"((a)[3]), "r"(b0v), "r"(b1v))

__device__ __forceinline__ uint32_t sw128(uint32_t off) { return off ^ ((off >> 3) & 0x70); }

__device__ __forceinline__ float gelu_f(float x) {
    float t = tanhf(0.79788456080286536f * (x + 0.044715f * x * x * x));
    return 0.5f * x * (1.0f + t);
}

union H4 { __half h[4]; uint2 u; };
union H2 { __half h[2]; uint32_t u; };

// ---------------- fused prologue: 4x weight transpose+convert + LN1, one launch ----------------
// wconv tile: 64 k-rows x 32 n-cols per block; stores are uint2 (128B/half-warp).
#define NB_WA 1536   // (3072/32)*(1024/64)
#define NB_WP 512    // (1024/32)*(1024/64)
#define NB_WF 2048   // (4096/32)*(1024/64)
#define NB_W2 2048   // (1024/32)*(4096/64)
#define NB_LN 8192
#define NB_TOTAL (NB_WA + NB_WP + NB_WF + NB_W2 + NB_LN)

__device__ __forceinline__ void wconv_body(const float* __restrict__ W,
    __half* __restrict__ Wf, int K, int N, int bid, float* t /* [64*33] */)
{
    int nblk = N >> 5;
    int n0 = (bid % nblk) * 32;
    int k0 = (bid / nblk) * 64;
    int tid = threadIdx.x;
    int tx = tid & 31, ty = tid >> 5;
    #pragma unroll
    for (int r = ty; r < 64; r += 8)
        t[r * 33 + tx] = W[(size_t)(k0 + r) * N + n0 + tx];
    __syncthreads();
    #pragma unroll
    for (int u = tid; u < 512; u += 256) {
        int n = u >> 4, kq = (u & 15) * 4;
        H4 h4;
        h4.h[0] = __float2half(t[(kq + 0) * 33 + n]);
        h4.h[1] = __float2half(t[(kq + 1) * 33 + n]);
        h4.h[2] = __float2half(t[(kq + 2) * 33 + n]);
        h4.h[3] = __float2half(t[(kq + 3) * 33 + n]);
        *(uint2*)(Wf + (size_t)(n0 + n) * K + k0 + kq) = h4.u;
    }
}

__device__ __forceinline__ void ln_body(const float* __restrict__ x,
    const float* __restrict__ g, const float* __restrict__ b,
    __half* __restrict__ oh, int row, float* red)
{
    int t = threadIdx.x;
    float4 v = ((const float4*)(x + (size_t)row * CEMB))[t];
    float s  = v.x + v.y + v.z + v.w;
    float ss = v.x*v.x + v.y*v.y + v.z*v.z + v.w*v.w;
    #pragma unroll
    for (int o = 16; o > 0; o >>= 1) {
        s  += __shfl_xor_sync(0xffffffffu, s,  o);
        ss += __shfl_xor_sync(0xffffffffu, ss, o);
    }
    int warp = t >> 5, lane = t & 31;
    if (lane == 0) { red[warp] = s; red[warp + 8] = ss; }
    __syncthreads();
    float sum = 0.f, sumsq = 0.f;
    #pragma unroll
    for (int w = 0; w < 8; w++) { sum += red[w]; sumsq += red[w + 8]; }
    float mu   = sum * (1.0f / CEMB);
    float var  = sumsq * (1.0f / CEMB) - mu * mu;
    float rstd = rsqrtf(var + 1e-5f);
    float4 gv = ((const float4*)g)[t];
    float4 bv = ((const float4*)b)[t];
    H4 o;
    o.h[0] = __float2half((v.x - mu) * rstd * gv.x + bv.x);
    o.h[1] = __float2half((v.y - mu) * rstd * gv.y + bv.y);
    o.h[2] = __float2half((v.z - mu) * rstd * gv.z + bv.z);
    o.h[3] = __float2half((v.w - mu) * rstd * gv.w + bv.w);
    *(uint2*)(oh + (size_t)row * CEMB + t * 4) = o.u;
}

__global__ __launch_bounds__(256) void prologue_kernel(
    const float* __restrict__ w_attn, __half* __restrict__ wa,
    const float* __restrict__ w_proj, __half* __restrict__ wp,
    const float* __restrict__ w_fc,   __half* __restrict__ wf,
    const float* __restrict__ w_fc2,  __half* __restrict__ w2,
    const float* __restrict__ x, const float* __restrict__ ln1_g,
    const float* __restrict__ ln1_b, __half* __restrict__ h)
{
    __shared__ float t[64 * 33];
    int bid = blockIdx.x;
    if (bid < NB_WA) {
        wconv_body(w_attn, wa, CEMB, 3*CEMB, bid, t);
    } else if (bid < NB_WA + NB_WP) {
        wconv_body(w_proj, wp, CEMB, CEMB, bid - NB_WA, t);
    } else if (bid < NB_WA + NB_WP + NB_WF) {
        wconv_body(w_fc, wf, CEMB, DFF, bid - NB_WA - NB_WP, t);
    } else if (bid < NB_WA + NB_WP + NB_WF + NB_W2) {
        wconv_body(w_fc2, w2, DFF, CEMB, bid - NB_WA - NB_WP - NB_WF, t);
    } else {
        ln_body(x, ln1_g, ln1_b, h, bid - (NB_WA + NB_WP + NB_WF + NB_W2), t);
    }
}

// ---------------- LayerNorm -> fp16 (standalone, for ln2) ----------------
__global__ __launch_bounds__(256) void ln_kernel(const float* __restrict__ x,
                                                 const float* __restrict__ g,
                                                 const float* __restrict__ b,
                                                 __half* __restrict__ oh)
{
    __shared__ float red[16];
    ln_body(x, g, b, oh, blockIdx.x, red);
}

// ---------------- HMMA fp16 GEMM: C = A @ B^T + bias (champion config) ----------------
// 128x128 tile, 8 warps (4m x 2n), warp tile 32x64, 2-stage, occ 2.
// EPI: 1 = fp32 out + residual, 2 = gelu -> fp16, 4 = fp16 out w/ q-scale (QKV)
#define STAGE_BYTES 32768
#define SMEM_GEMM (2 * STAGE_BYTES + 1024)

template<int EPI>
__global__ __launch_bounds__(GT, 2) void gemm_f16(
    const __half* __restrict__ Ah,
    const __half* __restrict__ Bf,
    const float* __restrict__ bias, const float* __restrict__ R,
    float* __restrict__ Cf, __half* __restrict__ Ch,
    int M, int N, int K)
{
    extern __shared__ char dsm[];
    uintptr_t pa = ((uintptr_t)dsm + 1023) & ~(uintptr_t)1023;
    uint32_t sb = smem_u32((char*)pa);

    int tid = threadIdx.x;
    int wid = tid >> 5, lid = tid & 31;
    int wm = wid >> 1, wn = wid & 1;
    int m0 = blockIdx.y * BM, n0 = blockIdx.x * BN;

    const int NC = K / BKE;
    int lrow = tid >> 3;
    int lch  = tid & 7;

    auto load_stage = [&](int c) {
        int buf = c & 1;
        uint32_t st = sb + buf * STAGE_BYTES;
        int k0 = c * BKE;
        #pragma unroll
        for (int t = 0; t < 4; t++) {
            int row = lrow + t * 32;
            uint32_t so = sw128((uint32_t)(row * 128 + lch * 16));
            size_t ga = (size_t)(m0 + row) * K + k0 + lch * 8;
            CP_ASYNC16(st + so,         (const char*)(Ah + ga));
            size_t gb = (size_t)(n0 + row) * K + k0 + lch * 8;
            CP_ASYNC16(st + 16384 + so, (const char*)(Bf + gb));
        }
    };

    float acc[2][8][4];
    #pragma unroll
    for (int mi = 0; mi < 2; mi++)
        #pragma unroll
        for (int j = 0; j < 8; j++)
            #pragma unroll
            for (int q = 0; q < 4; q++) acc[mi][j][q] = 0.f;

    int lrow16 = lid & 15;
    int khalf  = lid >> 4;

    load_stage(0);
    CP_COMMIT();

    for (int c = 0; c < NC; c++) {
        if (c + 1 < NC) { load_stage(c + 1); CP_COMMIT(); CP_WAIT1(); }
        else            { CP_WAIT0(); }
        __syncthreads();

        uint32_t st = sb + (c & 1) * STAGE_BYTES;

        #pragma unroll
        for (int s = 0; s < 4; s++) {
            uint32_t aH[2][4], bH[4][4];
            #pragma unroll
            for (int mi = 0; mi < 2; mi++) {
                int row = wm * 32 + mi * 16 + lrow16;
                int ch = (s * 2 + khalf) ^ (row & 7);
                uint32_t ad = st + (uint32_t)(row * 128 + ch * 16);
                LDSM_X4(aH[mi][0], aH[mi][1], aH[mi][2], aH[mi][3], ad);
            }
            #pragma unroll
            for (int nb = 0; nb < 4; nb++) {
                int row = wn * 64 + nb * 16 + lrow16;
                int ch = (s * 2 + khalf) ^ (row & 7);
                uint32_t bd = st + 16384 + (uint32_t)(row * 128 + ch * 16);
                LDSM_X4(bH[nb][0], bH[nb][1], bH[nb][2], bH[nb][3], bd);
            }
            #pragma unroll
            for (int mi = 0; mi < 2; mi++) {
                #pragma unroll
                for (int nb = 0; nb < 4; nb++) {
                    MMAF16(acc[mi][nb*2],   aH[mi], bH[nb][0], bH[nb][2]);
                    MMAF16(acc[mi][nb*2+1], aH[mi], bH[nb][1], bH[nb][3]);
                }
            }
        }
        __syncthreads();
    }

    int gid = lid >> 2, tig = lid & 3;
    #pragma unroll
    for (int mi = 0; mi < 2; mi++) {
        #pragma unroll
        for (int j = 0; j < 8; j++) {
            int r0 = m0 + wm * 32 + mi * 16 + gid;
            int r1 = r0 + 8;
            int col = n0 + wn * 64 + j * 8 + tig * 2;
            float b0 = bias[col], b1 = bias[col + 1];
            float v0 = acc[mi][j][0] + b0, v1 = acc[mi][j][1] + b1;
            float v2 = acc[mi][j][2] + b0, v3 = acc[mi][j][3] + b1;
            if (EPI == 1) {
                float2 q0 = *(const float2*)(R + (size_t)r0 * N + col);
                float2 q1 = *(const float2*)(R + (size_t)r1 * N + col);
                v0 += q0.x; v1 += q0.y; v2 += q1.x; v3 += q1.y;
            }
            if (EPI == 2) {
                v0 = gelu_f(v0); v1 = gelu_f(v1); v2 = gelu_f(v2); v3 = gelu_f(v3);
            }
            if (EPI == 4) {
                float sc = (col < CEMB) ? 0.125f : 1.0f;   // pre-scale q columns
                v0 *= sc; v1 *= sc; v2 *= sc; v3 *= sc;
            }
            if (EPI == 2 || EPI == 4) {
                H2 h0, h1;
                h0.h[0] = __float2half(v0); h0.h[1] = __float2half(v1);
                h1.h[0] = __float2half(v2); h1.h[1] = __float2half(v3);
                *(uint32_t*)(Ch + (size_t)r0 * N + col) = h0.u;
                *(uint32_t*)(Ch + (size_t)r1 * N + col) = h1.u;
            } else {
                *(float2*)(Cf + (size_t)r0 * N + col) = make_float2(v0, v1);
                *(float2*)(Cf + (size_t)r1 * N + col) = make_float2(v2, v3);
            }
        }
    }
}

// ---------------- HMMA flash attention: P in registers (FA2), V via trans-LDSM ----------------
// smem: Q 16K @0 | buf(b) @16K+16K*b: K 8K, V 8K = 48KB, occ 2
#define ATSM_BUF(b) (16384 + (b) * 16384)
#define ATT_SMEM (49152 + 1024)

__global__ __launch_bounds__(256, 2) void attn_mma_kernel(
    const __half* __restrict__ qkv,
    __half* __restrict__ yo)
{
    extern __shared__ char dsm[];
    uintptr_t pa = ((uintptr_t)dsm + 1023) & ~(uintptr_t)1023;
    uint32_t sb = smem_u32((char*)pa);

    int qt = gridDim.x - 1 - blockIdx.x;
    int q0 = qt * 128;
    int bh = blockIdx.y;
    int b = bh >> 4, hd = bh & 15;
    const __half* qbase = qkv + (size_t)b * TT * RS + hd * HS;

    int tid = threadIdx.x;
    int wid = tid >> 5, lid = tid & 31;
    int lrow16 = lid & 15, khalf = lid >> 4;
    int arow = wid * 16 + lrow16;
    int vrow_in = ((lid >> 4) << 3) + (lid & 7);
    int vhalf   = (lid >> 3) & 1;

    auto load_kv = [&](int jb, int buf) {
        int j0 = jb * 64;
        uint32_t st = sb + ATSM_BUF(buf);
        const __half* kf = qbase + CEMB;
        const __half* vf = qbase + 2 * CEMB;
        #pragma unroll
        for (int i = tid; i < 512; i += 256) {
            int row = i >> 3, ch = i & 7;
            uint32_t so = sw128((uint32_t)(row * 128 + ch * 16));
            size_t go = (size_t)(j0 + row) * RS + ch * 8;
            CP_ASYNC16(st + so,        (const char*)(kf + go));
            CP_ASYNC16(st + 8192 + so, (const char*)(vf + go));
        }
    };

    {
        #pragma unroll
        for (int i = tid; i < 1024; i += 256) {
            int row = i >> 3, ch = i & 7;
            uint32_t so = sw128((uint32_t)(row * 128 + ch * 16));
            CP_ASYNC16(sb + so, (const char*)(qbase + (size_t)(q0 + row) * RS + ch * 8));
        }
    }
    load_kv(0, 0);
    CP_COMMIT();

    float m_[2] = {-INFINITY, -INFINITY};
    float l_[2] = {0.f, 0.f};
    float acc[8][4];
    #pragma unroll
    for (int nb = 0; nb < 8; nb++)
        #pragma unroll
        for (int q = 0; q < 4; q++) acc[nb][q] = 0.f;

    int jbmax = q0 / 64 + 1;
    for (int jb = 0; jb <= jbmax; jb++) {
        int buf = jb & 1;
        CP_WAIT0();
        __syncthreads();
        if (jb < jbmax) { load_kv(jb + 1, buf ^ 1); CP_COMMIT(); }

        uint32_t sK = sb + ATSM_BUF(buf);
        uint32_t sV = sK + 8192;

        float s[8][4];
        #pragma unroll
        for (int nb = 0; nb < 8; nb++)
            #pragma unroll
            for (int q = 0; q < 4; q++) s[nb][q] = 0.f;

        #pragma unroll
        for (int ks = 0; ks < 4; ks++) {
            int ach = (ks * 2 + khalf) ^ (arow & 7);
            uint32_t aa = sb + (uint32_t)(arow * 128 + ach * 16);
            uint32_t aH[4];
            LDSM_X4(aH[0], aH[1], aH[2], aH[3], aa);
            uint32_t bH[4][4];
            #pragma unroll
            for (int nb2 = 0; nb2 < 4; nb2++) {
                int br = nb2 * 16 + lrow16;
                int bch = (ks * 2 + khalf) ^ (br & 7);
                uint32_t ba = sK + (uint32_t)(br * 128 + bch * 16);
                LDSM_X4(bH[nb2][0], bH[nb2][1], bH[nb2][2], bH[nb2][3], ba);
            }
            #pragma unroll
            for (int nb2 = 0; nb2 < 4; nb2++) {
                MMAF16(s[nb2*2],   aH, bH[nb2][0], bH[nb2][2]);
                MMAF16(s[nb2*2+1], aH, bH[nb2][1], bH[nb2][3]);
            }
        }

        int j0 = jb * 64;
        if (j0 + 63 > q0 + wid * 16) {
            int r0g = q0 + wid * 16 + (lid >> 2);
            #pragma unroll
            for (int nb = 0; nb < 8; nb++) {
                int c0 = j0 + nb * 8 + (lid & 3) * 2;
                if (c0     > r0g)     s[nb][0] = -INFINITY;
                if (c0 + 1 > r0g)     s[nb][1] = -INFINITY;
                if (c0     > r0g + 8) s[nb][2] = -INFINITY;
                if (c0 + 1 > r0g + 8) s[nb][3] = -INFINITY;
            }
        }

        float rmax[2] = {-INFINITY, -INFINITY};
        #pragma unroll
        for (int nb = 0; nb < 8; nb++) {
            rmax[0] = fmaxf(rmax[0], fmaxf(s[nb][0], s[nb][1]));
            rmax[1] = fmaxf(rmax[1], fmaxf(s[nb][2], s[nb][3]));
        }
        #pragma unroll
        for (int o = 1; o <= 2; o <<= 1) {
            rmax[0] = fmaxf(rmax[0], __shfl_xor_sync(0xffffffffu, rmax[0], o));
            rmax[1] = fmaxf(rmax[1], __shfl_xor_sync(0xffffffffu, rmax[1], o));
        }
        float mn0 = fmaxf(m_[0], rmax[0]);
        float mn1 = fmaxf(m_[1], rmax[1]);
        float alpha0 = __expf(m_[0] - mn0);
        float alpha1 = __expf(m_[1] - mn1);
        m_[0] = mn0; m_[1] = mn1;
        float rs[2] = {0.f, 0.f};
        #pragma unroll
        for (int nb = 0; nb < 8; nb++) {
            s[nb][0] = __expf(s[nb][0] - mn0); rs[0] += s[nb][0];
            s[nb][1] = __expf(s[nb][1] - mn0); rs[0] += s[nb][1];
            s[nb][2] = __expf(s[nb][2] - mn1); rs[1] += s[nb][2];
            s[nb][3] = __expf(s[nb][3] - mn1); rs[1] += s[nb][3];
        }
        #pragma unroll
        for (int o = 1; o <= 2; o <<= 1) {
            rs[0] += __shfl_xor_sync(0xffffffffu, rs[0], o);
            rs[1] += __shfl_xor_sync(0xffffffffu, rs[1], o);
        }
        l_[0] = l_[0] * alpha0 + rs[0];
        l_[1] = l_[1] * alpha1 + rs[1];
        #pragma unroll
        for (int nb = 0; nb < 8; nb++) {
            acc[nb][0] *= alpha0; acc[nb][1] *= alpha0;
            acc[nb][2] *= alpha1; acc[nb][3] *= alpha1;
        }

        // P -> fp16 A-fragments in registers
        uint32_t pH[4][4];
        #pragma unroll
        for (int ks = 0; ks < 4; ks++) {
            H2 t0, t1, t2, t3;
            t0.h[0] = __float2half(s[2*ks][0]);   t0.h[1] = __float2half(s[2*ks][1]);
            t1.h[0] = __float2half(s[2*ks][2]);   t1.h[1] = __float2half(s[2*ks][3]);
            t2.h[0] = __float2half(s[2*ks+1][0]); t2.h[1] = __float2half(s[2*ks+1][1]);
            t3.h[0] = __float2half(s[2*ks+1][2]); t3.h[1] = __float2half(s[2*ks+1][3]);
            pH[ks][0] = t0.u; pH[ks][1] = t1.u; pH[ks][2] = t2.u; pH[ks][3] = t3.u;
        }

        #pragma unroll
        for (int ks = 0; ks < 4; ks++) {
            uint32_t bH[4][4];
            int trow = ks * 16 + vrow_in;
            #pragma unroll
            for (int nb2 = 0; nb2 < 4; nb2++) {
                int chunk = nb2 * 2 + vhalf;
                uint32_t ba = sV + (uint32_t)(trow * 128 + ((chunk ^ (trow & 7)) * 16));
                LDSM_X4_T(bH[nb2][0], bH[nb2][1], bH[nb2][2], bH[nb2][3], ba);
            }
            #pragma unroll
            for (int nb2 = 0; nb2 < 4; nb2++) {
                MMAF16(acc[nb2*2],   pH[ks], bH[nb2][0], bH[nb2][2]);
                MMAF16(acc[nb2*2+1], pH[ks], bH[nb2][1], bH[nb2][3]);
            }
        }
    }

    float inv0 = 1.0f / l_[0];
    float inv1 = 1.0f / l_[1];
    size_t r0g = (size_t)b * TT + q0 + wid * 16 + (lid >> 2);
    #pragma unroll
    for (int nb = 0; nb < 8; nb++) {
        int col = hd * HS + nb * 8 + (lid & 3) * 2;
        H2 h;
        h.h[0] = __float2half(acc[nb][0] * inv0);
        h.h[1] = __float2half(acc[nb][1] * inv0);
        *(uint32_t*)(yo + r0g * CEMB + col) = h.u;
        h.h[0] = __float2half(acc[nb][2] * inv1);
        h.h[1] = __float2half(acc[nb][3] * inv1);
        *(uint32_t*)(yo + (r0g + 8) * CEMB + col) = h.u;
    }
}

// ---------------- launch ----------------
extern "C" void kernel_launch(void* const* d_in, const int* in_sizes, int n_in,
                              void* d_out, int out_size)
{
    const float* x      = (const float*)d_in[0];
    const float* ln1_g  = (const float*)d_in[1];
    const float* ln1_b  = (const float*)d_in[2];
    const float* w_attn = (const float*)d_in[3];
    const float* b_attn = (const float*)d_in[4];
    const float* w_proj = (const float*)d_in[5];
    const float* b_proj = (const float*)d_in[6];
    const float* ln2_g  = (const float*)d_in[7];
    const float* ln2_b  = (const float*)d_in[8];
    const float* w_fc   = (const float*)d_in[9];
    const float* b_fc   = (const float*)d_in[10];
    const float* w_fc2  = (const float*)d_in[11];
    const float* b_fc2  = (const float*)d_in[12];
    float* out = (float*)d_out;

    float *x2;
    __half *qkv, *h, *y, *f;
    __half *wa, *wp, *wf, *w2;
    cudaGetSymbolAddress((void**)&qkv, g_qkv);
    cudaGetSymbolAddress((void**)&x2,  g_x2);
    cudaGetSymbolAddress((void**)&h,   g_h);
    cudaGetSymbolAddress((void**)&y,   g_y);
    cudaGetSymbolAddress((void**)&f,   g_f);
    cudaGetSymbolAddress((void**)&wa,  g_wa);
    cudaGetSymbolAddress((void**)&wp,  g_wp);
    cudaGetSymbolAddress((void**)&wf,  g_wf);
    cudaGetSymbolAddress((void**)&w2,  g_w2);

    cudaFuncSetAttribute(gemm_f16<1>, cudaFuncAttributeMaxDynamicSharedMemorySize, SMEM_GEMM);
    cudaFuncSetAttribute(gemm_f16<2>, cudaFuncAttributeMaxDynamicSharedMemorySize, SMEM_GEMM);
    cudaFuncSetAttribute(gemm_f16<4>, cudaFuncAttributeMaxDynamicSharedMemorySize, SMEM_GEMM);
    cudaFuncSetAttribute(attn_mma_kernel, cudaFuncAttributeMaxDynamicSharedMemorySize, ATT_SMEM);

    dim3 blk(256);

    // fused prologue: all weight conversions + ln1 in a single launch
    prologue_kernel<<<NB_TOTAL, blk>>>(w_attn, wa, w_proj, wp, w_fc, wf, w_fc2, w2,
                                       x, ln1_g, ln1_b, h);
    // qkv fp16 out, q columns pre-scaled by 0.125
    gemm_f16<4><<<dim3(3*CEMB/BN, MROWS/BM), GT, SMEM_GEMM>>>(
        h, wa, b_attn, nullptr, nullptr, qkv, MROWS, 3*CEMB, CEMB);
    attn_mma_kernel<<<dim3(TT/128, BB*NHEADS), blk, ATT_SMEM>>>(qkv, y);
    gemm_f16<1><<<dim3(CEMB/BN, MROWS/BM), GT, SMEM_GEMM>>>(
        y, wp, b_proj, x, x2, nullptr, MROWS, CEMB, CEMB);
    ln_kernel<<<MROWS, blk>>>(x2, ln2_g, ln2_b, h);
    gemm_f16<2><<<dim3(DFF/BN, MROWS/BM), GT, SMEM_GEMM>>>(
        h, wf, b_fc, nullptr, nullptr, f, MROWS, DFF, CEMB);
    gemm_f16<1><<<dim3(CEMB/BN, MROWS/BM), GT, SMEM_GEMM>>>(
        f, w2, b_fc2, x2, out, nullptr, MROWS, CEMB, DFF);
}